// round 13
// baseline (speedup 1.0000x reference)
#include <cuda_runtime.h>
#include <cstdint>

#define BATCH 4
#define HW    16384
#define CDIM  256
#define HEADS 8

__device__ float g_G[BATCH * CDIM * CDIM];
__device__ float g_WeffT[BATCH * CDIM * CDIM];   // Weff^T : [n][k]

__device__ __forceinline__ uint32_t f2tf(float x) {
    uint32_t r;
    asm("cvt.rna.tf32.f32 %0, %1;" : "=r"(r) : "f"(x));
    return r;
}

__device__ __forceinline__ void mma8(float* c, const uint32_t* a, const uint32_t* b) {
    asm volatile(
        "mma.sync.aligned.m16n8k8.row.col.f32.tf32.tf32.f32 "
        "{%0,%1,%2,%3}, {%4,%5,%6,%7}, {%8,%9}, {%0,%1,%2,%3};"
        : "+f"(c[0]), "+f"(c[1]), "+f"(c[2]), "+f"(c[3])
        : "r"(a[0]), "r"(a[1]), "r"(a[2]), "r"(a[3]), "r"(b[0]), "r"(b[1]));
}

__device__ __forceinline__ void cp16(uint32_t s, const float* g) {
    asm volatile("cp.async.cg.shared.global [%0], [%1], 16;" :: "r"(s), "l"(g));
}

// ---------------------------------------------------------------------------
// Gram: G[b] = X_b^T X_b.  R5-proven config: 256 threads, 128x128 CTA tile,
// warp 64x32, 3-stage cp.async, SYM 3-tile + mirror, split-K 16 (kChunk 1024).
// Plus diagonal B-aliasing (diag tiles skip B loads; Bb := Ab).
// ---------------------------------------------------------------------------
__global__ __launch_bounds__(256, 2) void gram_gemm(
    const float* __restrict__ xg, float* __restrict__ Gg, int kChunk)
{
    constexpr int AW = 4352;
    constexpr int BW = 4352;
    extern __shared__ float smem[];
    float* As = smem;
    float* Bs = smem + 3 * AW;

    const int tileId = blockIdx.x % 3;
    const int split  = blockIdx.x / 3;
    const int tm = (tileId == 2) ? 1 : 0;
    const int tn = (tileId == 0) ? 0 : 1;
    const bool same = (tm == tn);

    const float* A = xg + (long)blockIdx.z * HW * CDIM;
    float* Cp = Gg + (long)blockIdx.z * CDIM * CDIM;

    const int k0 = split * kChunk;

    const int tid  = threadIdx.x;
    const int lane = tid & 31;
    const int warp = tid >> 5;
    const int wm = warp >> 2;
    const int wn = warp & 3;
    const int g  = lane >> 2;
    const int t4 = lane & 3;

    const float* gA[4]; uint32_t sAoff[4];
    const float* gB[4];
#pragma unroll
    for (int r = 0; r < 4; r++) {
        int id = tid + r * 256;
        int k = id >> 5, m4 = (id & 31) << 2;
        gA[r] = A + (long)(k0 + k) * CDIM + tm * 128 + m4;
        sAoff[r] = k * 136 + m4;
        gB[r] = A + (long)(k0 + k) * CDIM + tn * 128 + m4;
    }
    const long stepA = (long)32 * CDIM;

    const uint32_t sAb = (uint32_t)__cvta_generic_to_shared(As);
    const uint32_t sBb = (uint32_t)__cvta_generic_to_shared(Bs);

    auto issue = [&](int buf) {
#pragma unroll
        for (int r = 0; r < 4; r++) { cp16(sAb + (buf * AW + sAoff[r]) * 4, gA[r]); gA[r] += stepA; }
        if (!same) {
#pragma unroll
            for (int r = 0; r < 4; r++) { cp16(sBb + (buf * BW + sAoff[r]) * 4, gB[r]); gB[r] += stepA; }
        }
        asm volatile("cp.async.commit_group;");
    };

    float acc[4][4][4];
#pragma unroll
    for (int i = 0; i < 4; i++)
#pragma unroll
        for (int j = 0; j < 4; j++)
#pragma unroll
            for (int r = 0; r < 4; r++) acc[i][j][r] = 0.f;

    const int T = kChunk >> 5;
    issue(0);
    if (T > 1) issue(1);
    int buf = 0;
    for (int t = 0; t < T; t++) {
        if (t + 2 < T) {
            issue((buf + 2) % 3);
            asm volatile("cp.async.wait_group 2;");
        } else if (t + 1 < T) {
            asm volatile("cp.async.wait_group 1;");
        } else {
            asm volatile("cp.async.wait_group 0;");
        }
        __syncthreads();
        const float* Ab = As + buf * AW;
        const float* Bb = same ? Ab : (Bs + buf * BW);
#pragma unroll
        for (int ks = 0; ks < 32; ks += 8) {
            uint32_t af[4][4], bf[4][2];
#pragma unroll
            for (int mi = 0; mi < 4; mi++) {
                int m0 = wm * 64 + mi * 16;
                af[mi][0] = f2tf(Ab[(ks + t4) * 136 + m0 + g]);
                af[mi][1] = f2tf(Ab[(ks + t4) * 136 + m0 + g + 8]);
                af[mi][2] = f2tf(Ab[(ks + t4 + 4) * 136 + m0 + g]);
                af[mi][3] = f2tf(Ab[(ks + t4 + 4) * 136 + m0 + g + 8]);
            }
#pragma unroll
            for (int ni = 0; ni < 4; ni++) {
                int n0 = wn * 32 + ni * 8;
                bf[ni][0] = f2tf(Bb[(ks + t4) * 136 + n0 + g]);
                bf[ni][1] = f2tf(Bb[(ks + t4 + 4) * 136 + n0 + g]);
            }
#pragma unroll
            for (int mi = 0; mi < 4; mi++)
#pragma unroll
                for (int ni = 0; ni < 4; ni++)
                    mma8(acc[mi][ni], af[mi], bf[ni]);
        }
        __syncthreads();
        buf = (buf + 1) % 3;
    }

    const bool mirror = (tm != tn);
#pragma unroll
    for (int mi = 0; mi < 4; mi++) {
#pragma unroll
        for (int ni = 0; ni < 4; ni++) {
            int row = (tm << 7) + wm * 64 + mi * 16 + g;
            int col = (tn << 7) + wn * 32 + ni * 8 + t4 * 2;
            atomicAdd(&Cp[(long)row * CDIM + col],           acc[mi][ni][0]);
            atomicAdd(&Cp[(long)row * CDIM + col + 1],       acc[mi][ni][1]);
            atomicAdd(&Cp[(long)(row + 8) * CDIM + col],     acc[mi][ni][2]);
            atomicAdd(&Cp[(long)(row + 8) * CDIM + col + 1], acc[mi][ni][3]);
            if (mirror) {
                atomicAdd(&Cp[(long)col * CDIM + row],           acc[mi][ni][0]);
                atomicAdd(&Cp[(long)(col + 1) * CDIM + row],     acc[mi][ni][1]);
                atomicAdd(&Cp[(long)col * CDIM + row + 8],       acc[mi][ni][2]);
                atomicAdd(&Cp[(long)(col + 1) * CDIM + row + 8], acc[mi][ni][3]);
            }
        }
    }
}

// ---------------------------------------------------------------------------
// out = X @ Weff.  R9-proven (70.0us measured): 128 threads, CTA 128x128,
// warp 64x64 (2x2), 2-stage cp.async, row stride 40, LDS.64 k-pairs.
// B (WeffT, [n][k]) pre-rounded by weff_cvt -> no B cvts.
// ---------------------------------------------------------------------------
__global__ __launch_bounds__(128, 2) void out_gemm(
    const float* __restrict__ xg, const float* __restrict__ wT,
    float* __restrict__ outg)
{
    extern __shared__ float smem[];
    float* As = smem;             // 2 stages x 128 x 40
    float* Bs = smem + 2 * 5120;

    const int tid  = threadIdx.x;
    const int lane = tid & 31;
    const int warp = tid >> 5;
    const int wm = warp >> 1, wn = warp & 1;
    const int g  = lane >> 2, t4 = lane & 3;
    const int b  = blockIdx.z;
    const int tm = blockIdx.x >> 1, tn = blockIdx.x & 1;

    const float* xb = xg + ((long)b * HW + (long)tm * 128) * CDIM;
    const float* wb = wT + (long)b * CDIM * CDIM + (long)tn * 128 * CDIM;

    const uint32_t sA = (uint32_t)__cvta_generic_to_shared(As);
    const uint32_t sB = (uint32_t)__cvta_generic_to_shared(Bs);

    auto issue = [&](int buf, int k0) {
#pragma unroll
        for (int r = 0; r < 8; r++) {
            int id  = tid + r * 128;
            int row = id >> 3, c = id & 7;
            cp16(sA + (buf * 5120 + row * 40 + c * 4) * 4,
                 xb + (long)row * CDIM + k0 + c * 4);
        }
#pragma unroll
        for (int r = 0; r < 8; r++) {
            int id  = tid + r * 128;
            int row = id >> 3, c = id & 7;
            cp16(sB + (buf * 5120 + row * 40 + c * 4) * 4,
                 wb + (long)row * CDIM + k0 + c * 4);
        }
        asm volatile("cp.async.commit_group;");
    };

    float acc[4][8][4];
#pragma unroll
    for (int i = 0; i < 4; i++)
#pragma unroll
        for (int j = 0; j < 8; j++)
#pragma unroll
            for (int r = 0; r < 4; r++) acc[i][j][r] = 0.f;

    const int T = 8;   // K = 256 = 8 x 32
    issue(0, 0);
    for (int t = 0; t < T; t++) {
        if (t + 1 < T) {
            issue((t + 1) & 1, (t + 1) * 32);
            asm volatile("cp.async.wait_group 1;");
        } else {
            asm volatile("cp.async.wait_group 0;");
        }
        __syncthreads();
        const float* Ab = As + (t & 1) * 5120;
        const float* Bb = Bs + (t & 1) * 5120;
#pragma unroll
        for (int ks = 0; ks < 32; ks += 8) {
            uint32_t af[4][4];
#pragma unroll
            for (int mi = 0; mi < 4; mi++) {
                int r1 = wm * 64 + mi * 16 + g;
                uint2 p1 = *(const uint2*)&Ab[r1 * 40 + ks + 2 * t4];
                uint2 p2 = *(const uint2*)&Ab[(r1 + 8) * 40 + ks + 2 * t4];
                af[mi][0] = f2tf(__uint_as_float(p1.x));
                af[mi][2] = f2tf(__uint_as_float(p1.y));
                af[mi][1] = f2tf(__uint_as_float(p2.x));
                af[mi][3] = f2tf(__uint_as_float(p2.y));
            }
#pragma unroll
            for (int ni = 0; ni < 8; ni++) {
                int nr = wn * 64 + ni * 8 + g;
                uint2 bv = *(const uint2*)&Bb[nr * 40 + ks + 2 * t4];
                uint32_t bf[2] = { bv.x, bv.y };
#pragma unroll
                for (int mi = 0; mi < 4; mi++)
                    mma8(acc[mi][ni], af[mi], bf);
            }
        }
        __syncthreads();
    }

    float* ob = outg + ((long)b * HW + (long)tm * 128) * CDIM + (long)tn * 128;
#pragma unroll
    for (int mi = 0; mi < 4; mi++) {
        int r1 = wm * 64 + mi * 16 + g;
#pragma unroll
        for (int ni = 0; ni < 8; ni++) {
            int cc = wn * 64 + ni * 8 + 2 * t4;
            *(float2*)&ob[(long)r1 * CDIM + cc]       = make_float2(acc[mi][ni][0], acc[mi][ni][1]);
            *(float2*)&ob[(long)(r1 + 8) * CDIM + cc] = make_float2(acc[mi][ni][2], acc[mi][ni][3]);
        }
    }
}

// In-place RNA-round WeffT to tf32.
__global__ void weff_cvt_kernel(float* w) {
    int i = blockIdx.x * blockDim.x + threadIdx.x;
    float4 v = ((float4*)w)[i];
    uint4 u;
    u.x = f2tf(v.x); u.y = f2tf(v.y); u.z = f2tf(v.z); u.w = f2tf(v.w);
    ((uint4*)w)[i] = u;
}

// ---------------------------------------------------------------------------
// Fused middle (R9-proven): one CTA per (head, batch). Emits Weff^T ([n][k]).
// ---------------------------------------------------------------------------
__global__ __launch_bounds__(256) void fused_middle(
    const float* __restrict__ Gg, const float* __restrict__ Wq,
    const float* __restrict__ Wk, const float* __restrict__ Wv,
    const float* __restrict__ Wout, float* __restrict__ WeffT)
{
    extern __shared__ uint32_t smw[];
    uint32_t* SW  = smw;
    uint32_t* SG  = smw + 18432;
    uint32_t* SQK = smw + 35072;
    float* SMM  = (float*)(smw + 53504);
    float* SATT = (float*)(smw + 54560);
    float* SDQ  = (float*)(smw + 55616);
    float* SDK  = (float*)(smw + 55648);

    const int h = blockIdx.x;
    const int b = blockIdx.z;
    const float* G = Gg + (long)b * CDIM * CDIM;
    float* Wf = WeffT + (long)b * CDIM * CDIM;

    const int tid  = threadIdx.x;
    const int lane = tid & 31;
    const int warp = tid >> 5;
    const int g  = lane >> 2;
    const int t4 = lane & 3;

    for (int i = tid; i < 256 * 64; i += 256) {
        int k = i >> 6, n = i & 63;
        float v = (n < 32) ? Wq[k * CDIM + h * 32 + n]
                           : Wk[k * CDIM + h * 32 + (n - 32)];
        SW[k * 72 + n] = f2tf(v);
    }
    __syncthreads();

    const int m0 = (warp & 3) * 16;
    const int n0 = (warp >> 2) * 32;
    for (int mb = 0; mb < 4; mb++) {
        for (int i = tid; i < 4096; i += 256) {
            int row = i >> 6, c4 = (i & 63) << 2;
            float4 v = *(const float4*)(G + (long)(mb * 64 + row) * 256 + c4);
            uint32_t* d = SG + row * 260 + c4;
            d[0] = f2tf(v.x); d[1] = f2tf(v.y); d[2] = f2tf(v.z); d[3] = f2tf(v.w);
        }
        __syncthreads();
        float acc[4][4];
#pragma unroll
        for (int i = 0; i < 4; i++)
#pragma unroll
            for (int r = 0; r < 4; r++) acc[i][r] = 0.f;
#pragma unroll 8
        for (int ks = 0; ks < 256; ks += 8) {
            uint32_t af[4], bf[4][2];
            af[0] = SG[(m0 + g) * 260 + ks + t4];
            af[1] = SG[(m0 + g + 8) * 260 + ks + t4];
            af[2] = SG[(m0 + g) * 260 + ks + t4 + 4];
            af[3] = SG[(m0 + g + 8) * 260 + ks + t4 + 4];
#pragma unroll
            for (int nf = 0; nf < 4; nf++) {
                int nn = n0 + nf * 8;
                bf[nf][0] = SW[(ks + t4) * 72 + nn + g];
                bf[nf][1] = SW[(ks + t4 + 4) * 72 + nn + g];
            }
#pragma unroll
            for (int nf = 0; nf < 4; nf++) mma8(acc[nf], af, bf[nf]);
        }
#pragma unroll
        for (int nf = 0; nf < 4; nf++) {
            int nn = n0 + nf * 8 + t4 * 2;
            int rr = mb * 64 + m0 + g;
            SQK[rr * 72 + nn]       = __float_as_uint(acc[nf][0]);
            SQK[rr * 72 + nn + 1]   = __float_as_uint(acc[nf][1]);
            SQK[(rr + 8) * 72 + nn]     = __float_as_uint(acc[nf][2]);
            SQK[(rr + 8) * 72 + nn + 1] = __float_as_uint(acc[nf][3]);
        }
        __syncthreads();
    }

    {
        int e = tid & 31, cb = warp * 4;
        float a0 = 0.f, a1 = 0.f, a2 = 0.f, a3 = 0.f;
        for (int m = 0; m < 256; m++) {
            float kv = __uint_as_float(SQK[m * 72 + 32 + e]);
            a0 += __uint_as_float(SW[m * 72 + cb + 0]) * kv;
            a1 += __uint_as_float(SW[m * 72 + cb + 1]) * kv;
            a2 += __uint_as_float(SW[m * 72 + cb + 2]) * kv;
            a3 += __uint_as_float(SW[m * 72 + cb + 3]) * kv;
        }
        SMM[(cb + 0) * 33 + e] = a0;
        SMM[(cb + 1) * 33 + e] = a1;
        SMM[(cb + 2) * 33 + e] = a2;
        SMM[(cb + 3) * 33 + e] = a3;
        if (tid < 32) {
            float d = 0.f;
            for (int m = 0; m < 256; m++)
                d += __uint_as_float(SW[m * 72 + tid]) * __uint_as_float(SQK[m * 72 + tid]);
            SDQ[tid] = d;
        } else if (tid < 64) {
            int e2 = tid - 32;
            float d = 0.f;
            for (int m = 0; m < 256; m++)
                d += __uint_as_float(SW[m * 72 + 32 + e2]) * __uint_as_float(SQK[m * 72 + 32 + e2]);
            SDK[e2] = d;
        }
    }
    __syncthreads();

    {
        float nk = rsqrtf(SDK[lane]);
#pragma unroll
        for (int r = 0; r < 4; r++) {
            int c = warp * 4 + r;
            float nq = rsqrtf(SDQ[c]);
            float l = SMM[c * 33 + lane] * nq * nk * (1.0f / 128.0f);
            float mx = l;
            for (int o = 16; o; o >>= 1) mx = fmaxf(mx, __shfl_xor_sync(0xffffffffu, mx, o));
            float p = __expf(l - mx);
            float s = p;
            for (int o = 16; o; o >>= 1) s += __shfl_xor_sync(0xffffffffu, s, o);
            SATT[c * 33 + lane] = p / s;
        }
    }
    __syncthreads();

    uint32_t* SWv = smw;
    uint32_t* SWx = smw + 9216;
    {
        float wo[32];
#pragma unroll
        for (int c = 0; c < 32; c++) wo[c] = Wout[(h * 32 + c) * CDIM + tid];
        for (int e = 0; e < 32; e++) {
            float a = 0.f;
#pragma unroll
            for (int c = 0; c < 32; c++) a += SATT[c * 33 + e] * wo[c];
            SWx[e * 264 + tid] = f2tf(a);
        }
        for (int i = tid; i < 8192; i += 256) {
            int m = i >> 5, e = i & 31;
            SWv[m * 36 + e] = f2tf(Wv[m * CDIM + h * 32 + e]);
        }
    }
    __syncthreads();

    {
        const int m0w = warp * 32;
        for (int nc = 0; nc < 4; nc++) {
            float acc[2][8][4];
#pragma unroll
            for (int mi = 0; mi < 2; mi++)
#pragma unroll
                for (int nf = 0; nf < 8; nf++)
#pragma unroll
                    for (int r = 0; r < 4; r++) acc[mi][nf][r] = 0.f;
#pragma unroll
            for (int ks = 0; ks < 32; ks += 8) {
                uint32_t af[2][4];
#pragma unroll
                for (int mi = 0; mi < 2; mi++) {
                    int mm = m0w + mi * 16;
                    af[mi][0] = SWv[(mm + g) * 36 + ks + t4];
                    af[mi][1] = SWv[(mm + g + 8) * 36 + ks + t4];
                    af[mi][2] = SWv[(mm + g) * 36 + ks + t4 + 4];
                    af[mi][3] = SWv[(mm + g + 8) * 36 + ks + t4 + 4];
                }
#pragma unroll
                for (int nf = 0; nf < 8; nf++) {
                    int nn = nc * 64 + nf * 8 + g;
                    uint32_t bf[2];
                    bf[0] = SWx[(ks + t4) * 264 + nn];
                    bf[1] = SWx[(ks + t4 + 4) * 264 + nn];
                    mma8(acc[0][nf], af[0], bf);
                    mma8(acc[1][nf], af[1], bf);
                }
            }
#pragma unroll
            for (int mi = 0; mi < 2; mi++) {
#pragma unroll
                for (int nf = 0; nf < 8; nf++) {
                    int rr = m0w + mi * 16 + g;
                    int cc = nc * 64 + nf * 8 + t4 * 2;
                    atomicAdd(&Wf[cc * 256 + rr],           acc[mi][nf][0]);
                    atomicAdd(&Wf[(cc + 1) * 256 + rr],     acc[mi][nf][1]);
                    atomicAdd(&Wf[cc * 256 + rr + 8],       acc[mi][nf][2]);
                    atomicAdd(&Wf[(cc + 1) * 256 + rr + 8], acc[mi][nf][3]);
                }
            }
        }
    }
}

// ---------------------------------------------------------------------------
extern "C" void kernel_launch(void* const* d_in, const int* in_sizes, int n_in,
                              void* d_out, int out_size) {
    (void)in_sizes; (void)n_in; (void)out_size;
    const float* x    = (const float*)d_in[0];
    const float* Wq   = (const float*)d_in[1];
    const float* Wk   = (const float*)d_in[2];
    const float* Wv   = (const float*)d_in[3];
    const float* Wout = (const float*)d_in[4];
    float* out = (float*)d_out;

    float *G, *WeffT;
    cudaGetSymbolAddress((void**)&G,     g_G);
    cudaGetSymbolAddress((void**)&WeffT, g_WeffT);

    const int smemGram  = 6 * 4352 * 4;     // 104448 (3 stages x (A+B))
    const int smemOut   = 4 * 5120 * 4;     // 81920  (2 stages x (A+B))
    const int smemFused = 55680 * 4;        // 222720

    cudaFuncSetAttribute(gram_gemm,
                         cudaFuncAttributeMaxDynamicSharedMemorySize, smemGram);
    cudaFuncSetAttribute(out_gemm,
                         cudaFuncAttributeMaxDynamicSharedMemorySize, smemOut);
    cudaFuncSetAttribute(fused_middle,
                         cudaFuncAttributeMaxDynamicSharedMemorySize, smemFused);

    cudaMemsetAsync(G,     0, BATCH * CDIM * CDIM * sizeof(float));
    cudaMemsetAsync(WeffT, 0, BATCH * CDIM * CDIM * sizeof(float));

    // G[b] = X_b^T X_b : 3 symmetric tiles x SPLIT-K 16 (kChunk 1024, R5-best)
    {
        dim3 gr(3 * 16, 1, BATCH);
        gram_gemm<<<gr, 256, smemGram>>>(x, G, 1024);
    }

    // fused middle -> WeffT
    {
        dim3 gr(HEADS, 1, BATCH);
        fused_middle<<<gr, 256, smemFused>>>(G, Wq, Wk, Wv, Wout, WeffT);
    }

    // pre-round WeffT to tf32 once (removes all B cvts from out_gemm)
    weff_cvt_kernel<<<(BATCH * CDIM * CDIM / 4) / 256, 256>>>(WeffT);

    // out = X @ Weff (R9-best: smem 2-stage, LDS.64 pairs)
    {
        dim3 gr(128 * 2, 1, BATCH);
        out_gemm<<<gr, 128, smemOut>>>(x, WeffT, out);
    }
}

// round 14
// speedup vs baseline: 1.0010x; 1.0010x over previous
#include <cuda_runtime.h>
#include <cstdint>

#define BATCH 4
#define HW    16384
#define CDIM  256
#define HEADS 8

__device__ float g_G[BATCH * CDIM * CDIM];
__device__ float g_Weff[BATCH * CDIM * CDIM];

__device__ __forceinline__ uint32_t f2tf(float x) {
    uint32_t r;
    asm("cvt.rna.tf32.f32 %0, %1;" : "=r"(r) : "f"(x));
    return r;
}

__device__ __forceinline__ void mma8(float* c, const uint32_t* a, const uint32_t* b) {
    asm volatile(
        "mma.sync.aligned.m16n8k8.row.col.f32.tf32.tf32.f32 "
        "{%0,%1,%2,%3}, {%4,%5,%6,%7}, {%8,%9}, {%0,%1,%2,%3};"
        : "+f"(c[0]), "+f"(c[1]), "+f"(c[2]), "+f"(c[3])
        : "r"(a[0]), "r"(a[1]), "r"(a[2]), "r"(a[3]), "r"(b[0]), "r"(b[1]));
}

__device__ __forceinline__ void cp16(uint32_t s, const float* g) {
    asm volatile("cp.async.cg.shared.global [%0], [%1], 16;" :: "r"(s), "l"(g));
}

// ---------------------------------------------------------------------------
// 3-stage cp.async tf32 GEMM, 128x128 CTA tile, 256 threads, 2 CTAs/SM.
//  TA    :  A is K-major ([k][m]) vs M-major ([m][k])
//  ATOMIC:  atomicAdd epilogue (split-K)
//  SYM   :  C symmetric (Gram): tiles (0,0),(0,1),(1,1); mirror off-diag.
//  CVTB  :  apply cvt.rna.tf32 to B fragments (false when B pre-rounded).
//  ALIAS :  diagonal SYM tiles alias B smem to A (MEASURED SLOWER - off).
// ---------------------------------------------------------------------------
template <bool TA, bool ATOMIC, bool SYM, bool CVTB, bool ALIAS>
__global__ __launch_bounds__(256, 2) void gemm_db(
    const float* __restrict__ Ag, const float* __restrict__ Bg,
    float* __restrict__ Cg, int Mdim, int Ndim, int Kdim,
    long sA, long sB, long sC, int kChunk)
{
    constexpr int AW = TA ? 4352 : 4608;
    constexpr int BW = 4352;
    extern __shared__ float smem[];
    float* As = smem;                 // 3 buffers
    float* Bs = smem + 3 * AW;

    int tm, tn, split;
    if (SYM) {
        const int tileId = blockIdx.x % 3;
        split = blockIdx.x / 3;
        tm = (tileId == 2) ? 1 : 0;
        tn = (tileId == 0) ? 0 : 1;
    } else {
        const int tilesN = Ndim >> 7;
        const int tilesM = Mdim >> 7;
        const int tileCount = tilesM * tilesN;
        const int tileId = blockIdx.x % tileCount;
        split = blockIdx.x / tileCount;
        tm = tileId / tilesN;
        tn = tileId % tilesN;
    }
    const bool same = ALIAS && SYM && (tm == tn);

    const float* A  = Ag + (long)blockIdx.z * sA;
    const float* Bp = Bg + (long)blockIdx.z * sB;
    float* Cp = Cg + (long)blockIdx.z * sC;

    const int k0 = split * kChunk;

    const int tid  = threadIdx.x;
    const int lane = tid & 31;
    const int warp = tid >> 5;
    const int wm = warp >> 2;
    const int wn = warp & 3;
    const int g  = lane >> 2;
    const int t4 = lane & 3;

    const float* gA[4]; uint32_t sAoff[4];
    const float* gB[4]; uint32_t sBoff[4];
#pragma unroll
    for (int r = 0; r < 4; r++) {
        int id = tid + r * 256;
        if (TA) {
            int k = id >> 5, m4 = (id & 31) << 2;
            gA[r] = A + (long)(k0 + k) * Mdim + (tm << 7) + m4;
            sAoff[r] = k * 136 + m4;
        } else {
            int m = id >> 3, k4 = (id & 7) << 2;
            gA[r] = A + (long)((tm << 7) + m) * Kdim + k0 + k4;
            sAoff[r] = m * 36 + k4;
        }
        int k = id >> 5, n4 = (id & 31) << 2;
        gB[r] = Bp + (long)(k0 + k) * Ndim + (tn << 7) + n4;
        sBoff[r] = k * 136 + n4;
    }
    const long stepA = TA ? (long)32 * Mdim : 32L;
    const long stepB = (long)32 * Ndim;

    const uint32_t sAb = (uint32_t)__cvta_generic_to_shared(As);
    const uint32_t sBb = (uint32_t)__cvta_generic_to_shared(Bs);

    auto issue = [&](int buf) {
#pragma unroll
        for (int r = 0; r < 4; r++) { cp16(sAb + (buf * AW + sAoff[r]) * 4, gA[r]); gA[r] += stepA; }
        if (!same) {
#pragma unroll
            for (int r = 0; r < 4; r++) { cp16(sBb + (buf * BW + sBoff[r]) * 4, gB[r]); gB[r] += stepB; }
        }
        asm volatile("cp.async.commit_group;");
    };

    float acc[4][4][4];
#pragma unroll
    for (int i = 0; i < 4; i++)
#pragma unroll
        for (int j = 0; j < 4; j++)
#pragma unroll
            for (int r = 0; r < 4; r++) acc[i][j][r] = 0.f;

    const int T = kChunk >> 5;
    issue(0);
    if (T > 1) issue(1);
    int buf = 0;
    for (int t = 0; t < T; t++) {
        if (t + 2 < T) {
            issue((buf + 2) % 3);
            asm volatile("cp.async.wait_group 2;");
        } else if (t + 1 < T) {
            asm volatile("cp.async.wait_group 1;");
        } else {
            asm volatile("cp.async.wait_group 0;");
        }
        __syncthreads();
        const float* Ab = As + buf * AW;
        const float* Bb = same ? Ab : (Bs + buf * BW);
#pragma unroll
        for (int ks = 0; ks < 32; ks += 8) {
            uint32_t af[4][4], bf[4][2];
#pragma unroll
            for (int mi = 0; mi < 4; mi++) {
                int m0 = wm * 64 + mi * 16;
                if (TA) {
                    af[mi][0] = f2tf(Ab[(ks + t4) * 136 + m0 + g]);
                    af[mi][1] = f2tf(Ab[(ks + t4) * 136 + m0 + g + 8]);
                    af[mi][2] = f2tf(Ab[(ks + t4 + 4) * 136 + m0 + g]);
                    af[mi][3] = f2tf(Ab[(ks + t4 + 4) * 136 + m0 + g + 8]);
                } else {
                    af[mi][0] = f2tf(Ab[(m0 + g) * 36 + ks + t4]);
                    af[mi][1] = f2tf(Ab[(m0 + g + 8) * 36 + ks + t4]);
                    af[mi][2] = f2tf(Ab[(m0 + g) * 36 + ks + t4 + 4]);
                    af[mi][3] = f2tf(Ab[(m0 + g + 8) * 36 + ks + t4 + 4]);
                }
            }
#pragma unroll
            for (int ni = 0; ni < 4; ni++) {
                int n0 = wn * 32 + ni * 8;
                if (CVTB) {
                    bf[ni][0] = f2tf(Bb[(ks + t4) * 136 + n0 + g]);
                    bf[ni][1] = f2tf(Bb[(ks + t4 + 4) * 136 + n0 + g]);
                } else {
                    bf[ni][0] = __float_as_uint(Bb[(ks + t4) * 136 + n0 + g]);
                    bf[ni][1] = __float_as_uint(Bb[(ks + t4 + 4) * 136 + n0 + g]);
                }
            }
#pragma unroll
            for (int mi = 0; mi < 4; mi++)
#pragma unroll
                for (int ni = 0; ni < 4; ni++)
                    mma8(acc[mi][ni], af[mi], bf[ni]);
        }
        __syncthreads();
        buf = (buf + 1) % 3;
    }

    const bool mirror = SYM && (tm != tn);
#pragma unroll
    for (int mi = 0; mi < 4; mi++) {
#pragma unroll
        for (int ni = 0; ni < 4; ni++) {
            int row = (tm << 7) + wm * 64 + mi * 16 + g;
            int col = (tn << 7) + wn * 32 + ni * 8 + t4 * 2;
            float* p = Cp + (long)row * Ndim + col;
            if (ATOMIC) {
                atomicAdd(p,                acc[mi][ni][0]);
                atomicAdd(p + 1,            acc[mi][ni][1]);
                atomicAdd(p + 8 * Ndim,     acc[mi][ni][2]);
                atomicAdd(p + 8 * Ndim + 1, acc[mi][ni][3]);
                if (mirror) {
                    atomicAdd(Cp + (long)col * Ndim + row,             acc[mi][ni][0]);
                    atomicAdd(Cp + (long)(col + 1) * Ndim + row,       acc[mi][ni][1]);
                    atomicAdd(Cp + (long)col * Ndim + row + 8,         acc[mi][ni][2]);
                    atomicAdd(Cp + (long)(col + 1) * Ndim + row + 8,   acc[mi][ni][3]);
                }
            } else {
                p[0]            = acc[mi][ni][0];
                p[1]            = acc[mi][ni][1];
                p[8 * Ndim]     = acc[mi][ni][2];
                p[8 * Ndim + 1] = acc[mi][ni][3];
            }
        }
    }
}

// In-place round Weff to tf32 (RNA) so the out-GEMM skips per-fragment cvt.
__global__ void weff_cvt_kernel(float* w) {
    int i = blockIdx.x * blockDim.x + threadIdx.x;   // float4 index
    float4 v = ((float4*)w)[i];
    uint4 u;
    u.x = f2tf(v.x); u.y = f2tf(v.y); u.z = f2tf(v.z); u.w = f2tf(v.w);
    ((uint4*)w)[i] = u;
}

// ---------------------------------------------------------------------------
// Fused middle kernel: one CTA per (head, batch). Emits Weff (normal [k][n]).
// ---------------------------------------------------------------------------
__global__ __launch_bounds__(256) void fused_middle(
    const float* __restrict__ Gg, const float* __restrict__ Wq,
    const float* __restrict__ Wk, const float* __restrict__ Wv,
    const float* __restrict__ Wout, float* __restrict__ Weff)
{
    extern __shared__ uint32_t smw[];
    uint32_t* SW  = smw;
    uint32_t* SG  = smw + 18432;
    uint32_t* SQK = smw + 35072;
    float* SMM  = (float*)(smw + 53504);
    float* SATT = (float*)(smw + 54560);
    float* SDQ  = (float*)(smw + 55616);
    float* SDK  = (float*)(smw + 55648);

    const int h = blockIdx.x;
    const int b = blockIdx.z;
    const float* G = Gg + (long)b * CDIM * CDIM;
    float* Wf = Weff + (long)b * CDIM * CDIM;

    const int tid  = threadIdx.x;
    const int lane = tid & 31;
    const int warp = tid >> 5;
    const int g  = lane >> 2;
    const int t4 = lane & 3;

    for (int i = tid; i < 256 * 64; i += 256) {
        int k = i >> 6, n = i & 63;
        float v = (n < 32) ? Wq[k * CDIM + h * 32 + n]
                           : Wk[k * CDIM + h * 32 + (n - 32)];
        SW[k * 72 + n] = f2tf(v);
    }
    __syncthreads();

    const int m0 = (warp & 3) * 16;
    const int n0 = (warp >> 2) * 32;
    for (int mb = 0; mb < 4; mb++) {
        for (int i = tid; i < 4096; i += 256) {
            int row = i >> 6, c4 = (i & 63) << 2;
            float4 v = *(const float4*)(G + (long)(mb * 64 + row) * 256 + c4);
            uint32_t* d = SG + row * 260 + c4;
            d[0] = f2tf(v.x); d[1] = f2tf(v.y); d[2] = f2tf(v.z); d[3] = f2tf(v.w);
        }
        __syncthreads();
        float acc[4][4];
#pragma unroll
        for (int i = 0; i < 4; i++)
#pragma unroll
            for (int r = 0; r < 4; r++) acc[i][r] = 0.f;
#pragma unroll 8
        for (int ks = 0; ks < 256; ks += 8) {
            uint32_t af[4], bf[4][2];
            af[0] = SG[(m0 + g) * 260 + ks + t4];
            af[1] = SG[(m0 + g + 8) * 260 + ks + t4];
            af[2] = SG[(m0 + g) * 260 + ks + t4 + 4];
            af[3] = SG[(m0 + g + 8) * 260 + ks + t4 + 4];
#pragma unroll
            for (int nf = 0; nf < 4; nf++) {
                int nn = n0 + nf * 8;
                bf[nf][0] = SW[(ks + t4) * 72 + nn + g];
                bf[nf][1] = SW[(ks + t4 + 4) * 72 + nn + g];
            }
#pragma unroll
            for (int nf = 0; nf < 4; nf++) mma8(acc[nf], af, bf[nf]);
        }
#pragma unroll
        for (int nf = 0; nf < 4; nf++) {
            int nn = n0 + nf * 8 + t4 * 2;
            int rr = mb * 64 + m0 + g;
            SQK[rr * 72 + nn]       = __float_as_uint(acc[nf][0]);
            SQK[rr * 72 + nn + 1]   = __float_as_uint(acc[nf][1]);
            SQK[(rr + 8) * 72 + nn]     = __float_as_uint(acc[nf][2]);
            SQK[(rr + 8) * 72 + nn + 1] = __float_as_uint(acc[nf][3]);
        }
        __syncthreads();
    }

    {
        int e = tid & 31, cb = warp * 4;
        float a0 = 0.f, a1 = 0.f, a2 = 0.f, a3 = 0.f;
        for (int m = 0; m < 256; m++) {
            float kv = __uint_as_float(SQK[m * 72 + 32 + e]);
            a0 += __uint_as_float(SW[m * 72 + cb + 0]) * kv;
            a1 += __uint_as_float(SW[m * 72 + cb + 1]) * kv;
            a2 += __uint_as_float(SW[m * 72 + cb + 2]) * kv;
            a3 += __uint_as_float(SW[m * 72 + cb + 3]) * kv;
        }
        SMM[(cb + 0) * 33 + e] = a0;
        SMM[(cb + 1) * 33 + e] = a1;
        SMM[(cb + 2) * 33 + e] = a2;
        SMM[(cb + 3) * 33 + e] = a3;
        if (tid < 32) {
            float d = 0.f;
            for (int m = 0; m < 256; m++)
                d += __uint_as_float(SW[m * 72 + tid]) * __uint_as_float(SQK[m * 72 + tid]);
            SDQ[tid] = d;
        } else if (tid < 64) {
            int e2 = tid - 32;
            float d = 0.f;
            for (int m = 0; m < 256; m++)
                d += __uint_as_float(SW[m * 72 + 32 + e2]) * __uint_as_float(SQK[m * 72 + 32 + e2]);
            SDK[e2] = d;
        }
    }
    __syncthreads();

    {
        float nk = rsqrtf(SDK[lane]);
#pragma unroll
        for (int r = 0; r < 4; r++) {
            int c = warp * 4 + r;
            float nq = rsqrtf(SDQ[c]);
            float l = SMM[c * 33 + lane] * nq * nk * (1.0f / 128.0f);
            float mx = l;
            for (int o = 16; o; o >>= 1) mx = fmaxf(mx, __shfl_xor_sync(0xffffffffu, mx, o));
            float p = __expf(l - mx);
            float s = p;
            for (int o = 16; o; o >>= 1) s += __shfl_xor_sync(0xffffffffu, s, o);
            SATT[c * 33 + lane] = p / s;
        }
    }
    __syncthreads();

    uint32_t* SWv = smw;
    uint32_t* SWx = smw + 9216;
    {
        float wo[32];
#pragma unroll
        for (int c = 0; c < 32; c++) wo[c] = Wout[(h * 32 + c) * CDIM + tid];
        for (int e = 0; e < 32; e++) {
            float a = 0.f;
#pragma unroll
            for (int c = 0; c < 32; c++) a += SATT[c * 33 + e] * wo[c];
            SWx[e * 264 + tid] = f2tf(a);
        }
        for (int i = tid; i < 8192; i += 256) {
            int m = i >> 5, e = i & 31;
            SWv[m * 36 + e] = f2tf(Wv[m * CDIM + h * 32 + e]);
        }
    }
    __syncthreads();

    {
        const int m0w = warp * 32;
        for (int nc = 0; nc < 4; nc++) {
            float acc[2][8][4];
#pragma unroll
            for (int mi = 0; mi < 2; mi++)
#pragma unroll
                for (int nf = 0; nf < 8; nf++)
#pragma unroll
                    for (int r = 0; r < 4; r++) acc[mi][nf][r] = 0.f;
#pragma unroll
            for (int ks = 0; ks < 32; ks += 8) {
                uint32_t af[2][4];
#pragma unroll
                for (int mi = 0; mi < 2; mi++) {
                    int mm = m0w + mi * 16;
                    af[mi][0] = SWv[(mm + g) * 36 + ks + t4];
                    af[mi][1] = SWv[(mm + g + 8) * 36 + ks + t4];
                    af[mi][2] = SWv[(mm + g) * 36 + ks + t4 + 4];
                    af[mi][3] = SWv[(mm + g + 8) * 36 + ks + t4 + 4];
                }
#pragma unroll
                for (int nf = 0; nf < 8; nf++) {
                    int nn = nc * 64 + nf * 8 + g;
                    uint32_t bf[2];
                    bf[0] = SWx[(ks + t4) * 264 + nn];
                    bf[1] = SWx[(ks + t4 + 4) * 264 + nn];
                    mma8(acc[0][nf], af[0], bf);
                    mma8(acc[1][nf], af[1], bf);
                }
            }
#pragma unroll
            for (int mi = 0; mi < 2; mi++) {
#pragma unroll
                for (int nf = 0; nf < 8; nf++) {
                    int rr = m0w + mi * 16 + g;
                    int cc = nc * 64 + nf * 8 + t4 * 2;
                    atomicAdd(&Wf[rr * 256 + cc],           acc[mi][nf][0]);
                    atomicAdd(&Wf[rr * 256 + cc + 1],       acc[mi][nf][1]);
                    atomicAdd(&Wf[(rr + 8) * 256 + cc],     acc[mi][nf][2]);
                    atomicAdd(&Wf[(rr + 8) * 256 + cc + 1], acc[mi][nf][3]);
                }
            }
        }
    }
}

// ---------------------------------------------------------------------------
extern "C" void kernel_launch(void* const* d_in, const int* in_sizes, int n_in,
                              void* d_out, int out_size) {
    (void)in_sizes; (void)n_in; (void)out_size;
    const float* x    = (const float*)d_in[0];
    const float* Wq   = (const float*)d_in[1];
    const float* Wk   = (const float*)d_in[2];
    const float* Wv   = (const float*)d_in[3];
    const float* Wout = (const float*)d_in[4];
    float* out = (float*)d_out;

    float *G, *Weff;
    cudaGetSymbolAddress((void**)&G,    g_G);
    cudaGetSymbolAddress((void**)&Weff, g_Weff);

    const long sX = (long)HW * CDIM;
    const long sM = (long)CDIM * CDIM;

    const int smemGram  = 3 * (4352 + 4352) * 4;   // 104448
    const int smemOut   = 3 * (4608 + 4352) * 4;   // 107520
    const int smemFused = 55680 * 4;               // 222720

    cudaFuncSetAttribute(gemm_db<true, true, true, true, false>,
                         cudaFuncAttributeMaxDynamicSharedMemorySize, smemGram);
    cudaFuncSetAttribute(gemm_db<false, false, false, false, false>,
                         cudaFuncAttributeMaxDynamicSharedMemorySize, smemOut);
    cudaFuncSetAttribute(fused_middle,
                         cudaFuncAttributeMaxDynamicSharedMemorySize, smemFused);

    cudaMemsetAsync(G,    0, BATCH * CDIM * CDIM * sizeof(float));
    cudaMemsetAsync(Weff, 0, BATCH * CDIM * CDIM * sizeof(float));

    // G[b] = X_b^T X_b : SYM 3-tile, split-K 16 (kChunk 1024), NO alias
    // (R5-measured-best gram: 68.9us)
    {
        dim3 gr(3 * 16, 1, BATCH);
        gemm_db<true, true, true, true, false><<<gr, 256, smemGram>>>(
            x, x, G, CDIM, CDIM, HW, sX, sX, sM, 1024);
    }

    // fused middle -> Weff (normal layout, coalesced atomics)
    {
        dim3 gr(HEADS, 1, BATCH);
        fused_middle<<<gr, 256, smemFused>>>(G, Wq, Wk, Wv, Wout, Weff);
    }

    // pre-round Weff to tf32 once (out-GEMM skips B-fragment cvt)
    weff_cvt_kernel<<<(BATCH * CDIM * CDIM / 4) / 256, 256>>>(Weff);

    // out = X @ Weff (K6-proven out config, 74.8us)
    {
        dim3 gr(128 * 2, 1, BATCH);
        gemm_db<false, false, false, false, false><<<gr, 256, smemOut>>>(
            x, Weff, out, HW, CDIM, CDIM, sX, sM, sX, CDIM);
    }
}

// round 15
// speedup vs baseline: 1.0764x; 1.0753x over previous
#include <cuda_runtime.h>
#include <cstdint>

#define BATCH 4
#define HW    16384
#define CDIM  256
#define HEADS 8

__device__ float g_G[BATCH * CDIM * CDIM];
__device__ float g_Weff[BATCH * CDIM * CDIM];
__device__ float g_WeffT[BATCH * CDIM * CDIM];           // [n][k] tf32-rounded
__device__ float g_Yqk[BATCH * HEADS * CDIM * 64];       // [bh][m][64] raw fp32

__device__ __forceinline__ uint32_t f2tf(float x) {
    uint32_t r;
    asm("cvt.rna.tf32.f32 %0, %1;" : "=r"(r) : "f"(x));
    return r;
}

__device__ __forceinline__ void mma8(float* c, const uint32_t* a, const uint32_t* b) {
    asm volatile(
        "mma.sync.aligned.m16n8k8.row.col.f32.tf32.tf32.f32 "
        "{%0,%1,%2,%3}, {%4,%5,%6,%7}, {%8,%9}, {%0,%1,%2,%3};"
        : "+f"(c[0]), "+f"(c[1]), "+f"(c[2]), "+f"(c[3])
        : "r"(a[0]), "r"(a[1]), "r"(a[2]), "r"(a[3]), "r"(b[0]), "r"(b[1]));
}

__device__ __forceinline__ void cp16(uint32_t s, const float* g) {
    asm volatile("cp.async.cg.shared.global [%0], [%1], 16;" :: "r"(s), "l"(g));
}

// ---------------------------------------------------------------------------
// Gram (R6-best config ~53us inferred): 3-stage cp.async, 256 threads,
// 128x128 tile, SYM 3-tile + mirror, diagonal B-alias, split-K 32.
// ---------------------------------------------------------------------------
__global__ __launch_bounds__(256, 2) void gram_gemm(
    const float* __restrict__ xg, float* __restrict__ Gg, int kChunk)
{
    constexpr int AW = 4352;
    constexpr int BW = 4352;
    extern __shared__ float smem[];
    float* As = smem;
    float* Bs = smem + 3 * AW;

    const int tileId = blockIdx.x % 3;
    const int split  = blockIdx.x / 3;
    const int tm = (tileId == 2) ? 1 : 0;
    const int tn = (tileId == 0) ? 0 : 1;
    const bool same = (tm == tn);

    const float* A = xg + (long)blockIdx.z * HW * CDIM;
    float* Cp = Gg + (long)blockIdx.z * CDIM * CDIM;

    const int k0 = split * kChunk;

    const int tid  = threadIdx.x;
    const int lane = tid & 31;
    const int warp = tid >> 5;
    const int wm = warp >> 2;
    const int wn = warp & 3;
    const int g  = lane >> 2;
    const int t4 = lane & 3;

    const float* gA[4]; uint32_t sAoff[4];
    const float* gB[4];
#pragma unroll
    for (int r = 0; r < 4; r++) {
        int id = tid + r * 256;
        int k = id >> 5, m4 = (id & 31) << 2;
        gA[r] = A + (long)(k0 + k) * CDIM + tm * 128 + m4;
        sAoff[r] = k * 136 + m4;
        gB[r] = A + (long)(k0 + k) * CDIM + tn * 128 + m4;
    }
    const long stepA = (long)32 * CDIM;

    const uint32_t sAb = (uint32_t)__cvta_generic_to_shared(As);
    const uint32_t sBb = (uint32_t)__cvta_generic_to_shared(Bs);

    auto issue = [&](int buf) {
#pragma unroll
        for (int r = 0; r < 4; r++) { cp16(sAb + (buf * AW + sAoff[r]) * 4, gA[r]); gA[r] += stepA; }
        if (!same) {
#pragma unroll
            for (int r = 0; r < 4; r++) { cp16(sBb + (buf * BW + sAoff[r]) * 4, gB[r]); gB[r] += stepA; }
        }
        asm volatile("cp.async.commit_group;");
    };

    float acc[4][4][4];
#pragma unroll
    for (int i = 0; i < 4; i++)
#pragma unroll
        for (int j = 0; j < 4; j++)
#pragma unroll
            for (int r = 0; r < 4; r++) acc[i][j][r] = 0.f;

    const int T = kChunk >> 5;
    issue(0);
    if (T > 1) issue(1);
    int buf = 0;
    for (int t = 0; t < T; t++) {
        if (t + 2 < T) {
            issue((buf + 2) % 3);
            asm volatile("cp.async.wait_group 2;");
        } else if (t + 1 < T) {
            asm volatile("cp.async.wait_group 1;");
        } else {
            asm volatile("cp.async.wait_group 0;");
        }
        __syncthreads();
        const float* Ab = As + buf * AW;
        const float* Bb = same ? Ab : (Bs + buf * BW);
#pragma unroll
        for (int ks = 0; ks < 32; ks += 8) {
            uint32_t af[4][4], bf[4][2];
#pragma unroll
            for (int mi = 0; mi < 4; mi++) {
                int m0 = wm * 64 + mi * 16;
                af[mi][0] = f2tf(Ab[(ks + t4) * 136 + m0 + g]);
                af[mi][1] = f2tf(Ab[(ks + t4) * 136 + m0 + g + 8]);
                af[mi][2] = f2tf(Ab[(ks + t4 + 4) * 136 + m0 + g]);
                af[mi][3] = f2tf(Ab[(ks + t4 + 4) * 136 + m0 + g + 8]);
            }
#pragma unroll
            for (int ni = 0; ni < 4; ni++) {
                int n0 = wn * 32 + ni * 8;
                bf[ni][0] = f2tf(Bb[(ks + t4) * 136 + n0 + g]);
                bf[ni][1] = f2tf(Bb[(ks + t4 + 4) * 136 + n0 + g]);
            }
#pragma unroll
            for (int mi = 0; mi < 4; mi++)
#pragma unroll
                for (int ni = 0; ni < 4; ni++)
                    mma8(acc[mi][ni], af[mi], bf[ni]);
        }
        __syncthreads();
        buf = (buf + 1) % 3;
    }

    const bool mirror = (tm != tn);
#pragma unroll
    for (int mi = 0; mi < 4; mi++) {
#pragma unroll
        for (int ni = 0; ni < 4; ni++) {
            int row = (tm << 7) + wm * 64 + mi * 16 + g;
            int col = (tn << 7) + wn * 32 + ni * 8 + t4 * 2;
            atomicAdd(&Cp[(long)row * CDIM + col],           acc[mi][ni][0]);
            atomicAdd(&Cp[(long)row * CDIM + col + 1],       acc[mi][ni][1]);
            atomicAdd(&Cp[(long)(row + 8) * CDIM + col],     acc[mi][ni][2]);
            atomicAdd(&Cp[(long)(row + 8) * CDIM + col + 1], acc[mi][ni][3]);
            if (mirror) {
                atomicAdd(&Cp[(long)col * CDIM + row],           acc[mi][ni][0]);
                atomicAdd(&Cp[(long)(col + 1) * CDIM + row],     acc[mi][ni][1]);
                atomicAdd(&Cp[(long)col * CDIM + row + 8],       acc[mi][ni][2]);
                atomicAdd(&Cp[(long)(col + 1) * CDIM + row + 8], acc[mi][ni][3]);
            }
        }
    }
}

// ---------------------------------------------------------------------------
// qk_kernel: Yqk[bh][rows mb*64..+64][0..63] = G(mb rows) @ [Wq_h | Wk_h].
// Grid (HEADS, 4, BATCH), 256 threads. Proven phase-1 math, 4x parallelism.
// ---------------------------------------------------------------------------
__global__ __launch_bounds__(256) void qk_kernel(
    const float* __restrict__ Gg, const float* __restrict__ Wq,
    const float* __restrict__ Wk, float* __restrict__ Yqk)
{
    extern __shared__ uint32_t smw[];
    uint32_t* SW = smw;           // 256 x 64, stride 72 = 18432 words (tf32)
    uint32_t* SG = smw + 18432;   // 64 x 256, stride 260 = 16640 words (tf32)

    const int h  = blockIdx.x;
    const int mb = blockIdx.y;
    const int b  = blockIdx.z;
    const int bh = b * HEADS + h;
    const float* G = Gg + (long)b * CDIM * CDIM;

    const int tid  = threadIdx.x;
    const int lane = tid & 31;
    const int warp = tid >> 5;
    const int g  = lane >> 2;
    const int t4 = lane & 3;

    for (int i = tid; i < 256 * 64; i += 256) {
        int k = i >> 6, n = i & 63;
        float v = (n < 32) ? Wq[k * CDIM + h * 32 + n]
                           : Wk[k * CDIM + h * 32 + (n - 32)];
        SW[k * 72 + n] = f2tf(v);
    }
    for (int i = tid; i < 4096; i += 256) {
        int row = i >> 6, c4 = (i & 63) << 2;
        float4 v = *(const float4*)(G + (long)(mb * 64 + row) * 256 + c4);
        uint32_t* d = SG + row * 260 + c4;
        d[0] = f2tf(v.x); d[1] = f2tf(v.y); d[2] = f2tf(v.z); d[3] = f2tf(v.w);
    }
    __syncthreads();

    const int m0 = (warp & 3) * 16;
    const int n0 = (warp >> 2) * 32;
    float acc[4][4];
#pragma unroll
    for (int i = 0; i < 4; i++)
#pragma unroll
        for (int r = 0; r < 4; r++) acc[i][r] = 0.f;
#pragma unroll 8
    for (int ks = 0; ks < 256; ks += 8) {
        uint32_t af[4], bf[4][2];
        af[0] = SG[(m0 + g) * 260 + ks + t4];
        af[1] = SG[(m0 + g + 8) * 260 + ks + t4];
        af[2] = SG[(m0 + g) * 260 + ks + t4 + 4];
        af[3] = SG[(m0 + g + 8) * 260 + ks + t4 + 4];
#pragma unroll
        for (int nf = 0; nf < 4; nf++) {
            int nn = n0 + nf * 8;
            bf[nf][0] = SW[(ks + t4) * 72 + nn + g];
            bf[nf][1] = SW[(ks + t4 + 4) * 72 + nn + g];
        }
#pragma unroll
        for (int nf = 0; nf < 4; nf++) mma8(acc[nf], af, bf[nf]);
    }

    float* Y = Yqk + (long)bh * 256 * 64;
#pragma unroll
    for (int nf = 0; nf < 4; nf++) {
        int nn = n0 + nf * 8 + t4 * 2;
        int rr = mb * 64 + m0 + g;
        *(float2*)&Y[rr * 64 + nn]       = make_float2(acc[nf][0], acc[nf][1]);
        *(float2*)&Y[(rr + 8) * 64 + nn] = make_float2(acc[nf][2], acc[nf][3]);
    }
}

// ---------------------------------------------------------------------------
// mid_kernel: per (h,b) CTA. Mm via mma, diag via unrolled segmented reduce,
// softmax, Wmix, Weff += Wv@Wmix (proven phases 4-5).
// smem (words): SW@0:18432, SY@18432:18432, SMM@36864:1056, SATT@37920:1056,
//               SDQ@38976:32, SDK@39008:32, DP@39040:256  -> 39296 w
// ---------------------------------------------------------------------------
__global__ __launch_bounds__(256) void mid_kernel(
    const float* __restrict__ Yqk, const float* __restrict__ Wq,
    const float* __restrict__ Wk, const float* __restrict__ Wv,
    const float* __restrict__ Wout, float* __restrict__ Weff)
{
    extern __shared__ uint32_t smw[];
    uint32_t* SW = smw;
    uint32_t* SY = smw + 18432;
    float* SMM  = (float*)(smw + 36864);
    float* SATT = (float*)(smw + 37920);
    float* SDQ  = (float*)(smw + 38976);
    float* SDK  = (float*)(smw + 39008);
    float* DP   = (float*)(smw + 39040);

    const int h = blockIdx.x;
    const int b = blockIdx.z;
    const int bh = b * HEADS + h;
    float* Wf = Weff + (long)b * CDIM * CDIM;

    const int tid  = threadIdx.x;
    const int lane = tid & 31;
    const int warp = tid >> 5;
    const int g  = lane >> 2;
    const int t4 = lane & 3;

    for (int i = tid; i < 256 * 64; i += 256) {
        int k = i >> 6, n = i & 63;
        float v = (n < 32) ? Wq[k * CDIM + h * 32 + n]
                           : Wk[k * CDIM + h * 32 + (n - 32)];
        SW[k * 72 + n] = f2tf(v);
    }
    const float* Y = Yqk + (long)bh * 256 * 64;
    for (int i = tid; i < 256 * 64; i += 256) {
        int m = i >> 6, n = i & 63;
        SY[m * 72 + n] = __float_as_uint(Y[i]);
    }
    __syncthreads();

    // Mm[c][e] = sum_m Wq[m][c] * K[m][e]  (mma: A = Wq^T k-major, B = K k-major)
    {
        const int c0 = (warp & 1) * 16;
        const int e0 = (warp >> 1) * 8;
        float macc[4] = {0.f, 0.f, 0.f, 0.f};
#pragma unroll 8
        for (int ks = 0; ks < 256; ks += 8) {
            uint32_t af[4], bf[2];
            af[0] = SW[(ks + t4) * 72 + c0 + g];
            af[1] = SW[(ks + t4) * 72 + c0 + g + 8];
            af[2] = SW[(ks + t4 + 4) * 72 + c0 + g];
            af[3] = SW[(ks + t4 + 4) * 72 + c0 + g + 8];
            bf[0] = f2tf(__uint_as_float(SY[(ks + t4) * 72 + 32 + e0 + g]));
            bf[1] = f2tf(__uint_as_float(SY[(ks + t4 + 4) * 72 + 32 + e0 + g]));
            mma8(macc, af, bf);
        }
        int cc = c0 + g, ee = e0 + 2 * t4;
        SMM[cc * 33 + ee]           = macc[0];
        SMM[cc * 33 + ee + 1]       = macc[1];
        SMM[(cc + 8) * 33 + ee]     = macc[2];
        SMM[(cc + 8) * 33 + ee + 1] = macc[3];
    }

    // diag partials: c in [0,64) covers q (0..31) and k (32..63)
    {
        int c = tid & 63, seg = tid >> 6;
        float s = 0.f;
        int mbeg = seg * 64;
#pragma unroll 8
        for (int m = 0; m < 64; m++)
            s += __uint_as_float(SW[(mbeg + m) * 72 + c]) *
                 __uint_as_float(SY[(mbeg + m) * 72 + c]);
        DP[seg * 64 + c] = s;
    }
    __syncthreads();
    if (tid < 32) {
        SDQ[tid] = DP[tid] + DP[64 + tid] + DP[128 + tid] + DP[192 + tid];
    } else if (tid < 64) {
        int c = tid;
        SDK[c - 32] = DP[c] + DP[64 + c] + DP[128 + c] + DP[192 + c];
    }
    __syncthreads();

    // softmax over e
    {
        float nk = rsqrtf(SDK[lane]);
#pragma unroll
        for (int r = 0; r < 4; r++) {
            int c = warp * 4 + r;
            float nq = rsqrtf(SDQ[c]);
            float l = SMM[c * 33 + lane] * nq * nk * (1.0f / 128.0f);
            float mx = l;
            for (int o = 16; o; o >>= 1) mx = fmaxf(mx, __shfl_xor_sync(0xffffffffu, mx, o));
            float p = __expf(l - mx);
            float s = p;
            for (int o = 16; o; o >>= 1) s += __shfl_xor_sync(0xffffffffu, s, o);
            SATT[c * 33 + lane] = p / s;
        }
    }
    __syncthreads();

    // phase 4: SWv (Wv_h, m-major str 36) + SWx (Wmix, k-major str 264) in SW region
    uint32_t* SWv = smw;
    uint32_t* SWx = smw + 9216;
    {
        float wo[32];
#pragma unroll
        for (int c = 0; c < 32; c++) wo[c] = Wout[(h * 32 + c) * CDIM + tid];
        for (int e = 0; e < 32; e++) {
            float a = 0.f;
#pragma unroll
            for (int c = 0; c < 32; c++) a += SATT[c * 33 + e] * wo[c];
            SWx[e * 264 + tid] = f2tf(a);
        }
        for (int i = tid; i < 8192; i += 256) {
            int m = i >> 5, e = i & 31;
            SWv[m * 36 + e] = f2tf(Wv[m * CDIM + h * 32 + e]);
        }
    }
    __syncthreads();

    // phase 5: Weff += Wv_h @ Wmix_h (256x256, K=32)
    {
        const int m0w = warp * 32;
        for (int nc = 0; nc < 4; nc++) {
            float acc[2][8][4];
#pragma unroll
            for (int mi = 0; mi < 2; mi++)
#pragma unroll
                for (int nf = 0; nf < 8; nf++)
#pragma unroll
                    for (int r = 0; r < 4; r++) acc[mi][nf][r] = 0.f;
#pragma unroll
            for (int ks = 0; ks < 32; ks += 8) {
                uint32_t af[2][4];
#pragma unroll
                for (int mi = 0; mi < 2; mi++) {
                    int mm = m0w + mi * 16;
                    af[mi][0] = SWv[(mm + g) * 36 + ks + t4];
                    af[mi][1] = SWv[(mm + g + 8) * 36 + ks + t4];
                    af[mi][2] = SWv[(mm + g) * 36 + ks + t4 + 4];
                    af[mi][3] = SWv[(mm + g + 8) * 36 + ks + t4 + 4];
                }
#pragma unroll
                for (int nf = 0; nf < 8; nf++) {
                    int nn = nc * 64 + nf * 8 + g;
                    uint32_t bf[2];
                    bf[0] = SWx[(ks + t4) * 264 + nn];
                    bf[1] = SWx[(ks + t4 + 4) * 264 + nn];
                    mma8(acc[0][nf], af[0], bf);
                    mma8(acc[1][nf], af[1], bf);
                }
            }
#pragma unroll
            for (int mi = 0; mi < 2; mi++) {
#pragma unroll
                for (int nf = 0; nf < 8; nf++) {
                    int rr = m0w + mi * 16 + g;
                    int cc = nc * 64 + nf * 8 + t4 * 2;
                    atomicAdd(&Wf[rr * 256 + cc],           acc[mi][nf][0]);
                    atomicAdd(&Wf[rr * 256 + cc + 1],       acc[mi][nf][1]);
                    atomicAdd(&Wf[(rr + 8) * 256 + cc],     acc[mi][nf][2]);
                    atomicAdd(&Wf[(rr + 8) * 256 + cc + 1], acc[mi][nf][3]);
                }
            }
        }
    }
}

// ---------------------------------------------------------------------------
// WeffT[b][n][k] = tf32_round(Weff[b][k][n])  (tiled transpose + RNA round)
// ---------------------------------------------------------------------------
__global__ void weffT_kernel(const float* __restrict__ Weff,
                             float* __restrict__ WeffT)
{
    __shared__ float t[32][33];
    const int x0 = blockIdx.x * 32;     // n-tile
    const int y0 = blockIdx.y * 32;     // k-tile
    const int b  = blockIdx.z;
    const float* Wi = Weff + (long)b * CDIM * CDIM;
    float* Wo = WeffT + (long)b * CDIM * CDIM;
    const int tx = threadIdx.x, ty = threadIdx.y;
    for (int j = ty; j < 32; j += 8)
        t[j][tx] = Wi[(y0 + j) * CDIM + x0 + tx];
    __syncthreads();
    for (int j = ty; j < 32; j += 8) {
        uint32_t r = f2tf(t[tx][j]);
        ((uint32_t*)Wo)[(x0 + j) * CDIM + y0 + tx] = r;
    }
}

// ---------------------------------------------------------------------------
// out = X @ Weff.  PROVEN 70.3us: 128 threads, CTA 128x128, warp 64x64,
// 2-stage cp.async, row stride 40, LDS.64 k-pairs, B = WeffT pre-rounded.
// ---------------------------------------------------------------------------
__global__ __launch_bounds__(128, 2) void out_gemm(
    const float* __restrict__ xg, const float* __restrict__ wT,
    float* __restrict__ outg)
{
    extern __shared__ float smem[];
    float* As = smem;             // 2 stages x 128 x 40
    float* Bs = smem + 2 * 5120;

    const int tid  = threadIdx.x;
    const int lane = tid & 31;
    const int warp = tid >> 5;
    const int wm = warp >> 1, wn = warp & 1;
    const int g  = lane >> 2, t4 = lane & 3;
    const int b  = blockIdx.z;
    const int tm = blockIdx.x >> 1, tn = blockIdx.x & 1;

    const float* xb = xg + ((long)b * HW + (long)tm * 128) * CDIM;
    const float* wb = wT + (long)b * CDIM * CDIM + (long)tn * 128 * CDIM;

    const uint32_t sA = (uint32_t)__cvta_generic_to_shared(As);
    const uint32_t sB = (uint32_t)__cvta_generic_to_shared(Bs);

    auto issue = [&](int buf, int k0) {
#pragma unroll
        for (int r = 0; r < 8; r++) {
            int id  = tid + r * 128;
            int row = id >> 3, c = id & 7;
            cp16(sA + (buf * 5120 + row * 40 + c * 4) * 4,
                 xb + (long)row * CDIM + k0 + c * 4);
        }
#pragma unroll
        for (int r = 0; r < 8; r++) {
            int id  = tid + r * 128;
            int row = id >> 3, c = id & 7;
            cp16(sB + (buf * 5120 + row * 40 + c * 4) * 4,
                 wb + (long)row * CDIM + k0 + c * 4);
        }
        asm volatile("cp.async.commit_group;");
    };

    float acc[4][8][4];
#pragma unroll
    for (int i = 0; i < 4; i++)
#pragma unroll
        for (int j = 0; j < 8; j++)
#pragma unroll
            for (int r = 0; r < 4; r++) acc[i][j][r] = 0.f;

    const int T = 8;   // K = 256 = 8 x 32
    issue(0, 0);
    for (int t = 0; t < T; t++) {
        if (t + 1 < T) {
            issue((t + 1) & 1, (t + 1) * 32);
            asm volatile("cp.async.wait_group 1;");
        } else {
            asm volatile("cp.async.wait_group 0;");
        }
        __syncthreads();
        const float* Ab = As + (t & 1) * 5120;
        const float* Bb = Bs + (t & 1) * 5120;
#pragma unroll
        for (int ks = 0; ks < 32; ks += 8) {
            uint32_t af[4][4];
#pragma unroll
            for (int mi = 0; mi < 4; mi++) {
                int r1 = wm * 64 + mi * 16 + g;
                uint2 p1 = *(const uint2*)&Ab[r1 * 40 + ks + 2 * t4];
                uint2 p2 = *(const uint2*)&Ab[(r1 + 8) * 40 + ks + 2 * t4];
                af[mi][0] = f2tf(__uint_as_float(p1.x));
                af[mi][2] = f2tf(__uint_as_float(p1.y));
                af[mi][1] = f2tf(__uint_as_float(p2.x));
                af[mi][3] = f2tf(__uint_as_float(p2.y));
            }
#pragma unroll
            for (int ni = 0; ni < 8; ni++) {
                int nr = wn * 64 + ni * 8 + g;
                uint2 bv = *(const uint2*)&Bb[nr * 40 + ks + 2 * t4];
                uint32_t bf[2] = { bv.x, bv.y };
#pragma unroll
                for (int mi = 0; mi < 4; mi++)
                    mma8(acc[mi][ni], af[mi], bf);
            }
        }
        __syncthreads();
    }

    float* ob = outg + ((long)b * HW + (long)tm * 128) * CDIM + (long)tn * 128;
#pragma unroll
    for (int mi = 0; mi < 4; mi++) {
        int r1 = wm * 64 + mi * 16 + g;
#pragma unroll
        for (int ni = 0; ni < 8; ni++) {
            int cc = wn * 64 + ni * 8 + 2 * t4;
            *(float2*)&ob[(long)r1 * CDIM + cc]       = make_float2(acc[mi][ni][0], acc[mi][ni][1]);
            *(float2*)&ob[(long)(r1 + 8) * CDIM + cc] = make_float2(acc[mi][ni][2], acc[mi][ni][3]);
        }
    }
}

// ---------------------------------------------------------------------------
extern "C" void kernel_launch(void* const* d_in, const int* in_sizes, int n_in,
                              void* d_out, int out_size) {
    (void)in_sizes; (void)n_in; (void)out_size;
    const float* x    = (const float*)d_in[0];
    const float* Wq   = (const float*)d_in[1];
    const float* Wk   = (const float*)d_in[2];
    const float* Wv   = (const float*)d_in[3];
    const float* Wout = (const float*)d_in[4];
    float* out = (float*)d_out;

    float *G, *Weff, *WeffT, *Yqk;
    cudaGetSymbolAddress((void**)&G,     g_G);
    cudaGetSymbolAddress((void**)&Weff,  g_Weff);
    cudaGetSymbolAddress((void**)&WeffT, g_WeffT);
    cudaGetSymbolAddress((void**)&Yqk,   g_Yqk);

    const int smemGram = 6 * 4352 * 4;    // 104448
    const int smemQK   = 35072 * 4;       // 140288
    const int smemMid  = 39296 * 4;       // 157184
    const int smemOut  = 4 * 5120 * 4;    // 81920

    cudaFuncSetAttribute(gram_gemm,
                         cudaFuncAttributeMaxDynamicSharedMemorySize, smemGram);
    cudaFuncSetAttribute(qk_kernel,
                         cudaFuncAttributeMaxDynamicSharedMemorySize, smemQK);
    cudaFuncSetAttribute(mid_kernel,
                         cudaFuncAttributeMaxDynamicSharedMemorySize, smemMid);
    cudaFuncSetAttribute(out_gemm,
                         cudaFuncAttributeMaxDynamicSharedMemorySize, smemOut);

    cudaMemsetAsync(G,    0, BATCH * CDIM * CDIM * sizeof(float));
    cudaMemsetAsync(Weff, 0, BATCH * CDIM * CDIM * sizeof(float));

    // G[b] = X_b^T X_b : R6-best config (splitK 32, kChunk 512, alias)
    {
        dim3 gr(3 * 32, 1, BATCH);
        gram_gemm<<<gr, 256, smemGram>>>(x, G, 512);
    }
    // Yqk = G @ [Wq_h|Wk_h]  (128 CTAs)
    {
        dim3 gr(HEADS, 4, BATCH);
        qk_kernel<<<gr, 256, smemQK>>>(G, Wq, Wk, Yqk);
    }
    // Mm/softmax/Wmix/Weff  (32 CTAs, mma-based Mm)
    {
        dim3 gr(HEADS, 1, BATCH);
        mid_kernel<<<gr, 256, smemMid>>>(Yqk, Wq, Wk, Wv, Wout, Weff);
    }
    // WeffT = round_tf32(Weff^T)
    {
        dim3 gr(8, 8, BATCH), bl(32, 8);
        weffT_kernel<<<gr, bl>>>(Weff, WeffT);
    }
    // out = X @ Weff  (proven 70.3us config)
    {
        dim3 gr(128 * 2, 1, BATCH);
        out_gemm<<<gr, 128, smemOut>>>(x, WeffT, out);
    }
}

// round 16
// speedup vs baseline: 1.2238x; 1.1370x over previous
#include <cuda_runtime.h>
#include <cuda_fp16.h>
#include <cstdint>

#define BATCH 4
#define HW    16384
#define CDIM  256
#define HEADS 8

__device__ float  g_G[BATCH * CDIM * CDIM];
__device__ float  g_Weff[BATCH * CDIM * CDIM];
__device__ __half g_WeffTh[BATCH * CDIM * CDIM];         // [n][k] fp16
__device__ float  g_Yqk[BATCH * HEADS * CDIM * 64];      // [bh][m][64] raw fp32

__device__ __forceinline__ uint32_t f2tf(float x) {
    uint32_t r;
    asm("cvt.rna.tf32.f32 %0, %1;" : "=r"(r) : "f"(x));
    return r;
}

__device__ __forceinline__ void mma8(float* c, const uint32_t* a, const uint32_t* b) {
    asm volatile(
        "mma.sync.aligned.m16n8k8.row.col.f32.tf32.tf32.f32 "
        "{%0,%1,%2,%3}, {%4,%5,%6,%7}, {%8,%9}, {%0,%1,%2,%3};"
        : "+f"(c[0]), "+f"(c[1]), "+f"(c[2]), "+f"(c[3])
        : "r"(a[0]), "r"(a[1]), "r"(a[2]), "r"(a[3]), "r"(b[0]), "r"(b[1]));
}

// fp16 mma, fp32 accumulate
__device__ __forceinline__ void mma16(float* c, uint32_t a0, uint32_t a1,
                                      uint32_t a2, uint32_t a3,
                                      uint32_t b0, uint32_t b1) {
    asm volatile(
        "mma.sync.aligned.m16n8k16.row.col.f32.f16.f16.f32 "
        "{%0,%1,%2,%3}, {%4,%5,%6,%7}, {%8,%9}, {%0,%1,%2,%3};"
        : "+f"(c[0]), "+f"(c[1]), "+f"(c[2]), "+f"(c[3])
        : "r"(a0), "r"(a1), "r"(a2), "r"(a3), "r"(b0), "r"(b1));
}

__device__ __forceinline__ void cp16(uint32_t s, const void* g) {
    asm volatile("cp.async.cg.shared.global [%0], [%1], 16;" :: "r"(s), "l"(g));
}

// ---------------------------------------------------------------------------
// Gram (R6-best config): 3-stage cp.async, 256 threads, 128x128 tile,
// SYM 3-tile + mirror, diagonal B-alias, split-K 32 (kChunk 512).
// ---------------------------------------------------------------------------
__global__ __launch_bounds__(256, 2) void gram_gemm(
    const float* __restrict__ xg, float* __restrict__ Gg, int kChunk)
{
    constexpr int AW = 4352;
    constexpr int BW = 4352;
    extern __shared__ float smem[];
    float* As = smem;
    float* Bs = smem + 3 * AW;

    const int tileId = blockIdx.x % 3;
    const int split  = blockIdx.x / 3;
    const int tm = (tileId == 2) ? 1 : 0;
    const int tn = (tileId == 0) ? 0 : 1;
    const bool same = (tm == tn);

    const float* A = xg + (long)blockIdx.z * HW * CDIM;
    float* Cp = Gg + (long)blockIdx.z * CDIM * CDIM;

    const int k0 = split * kChunk;

    const int tid  = threadIdx.x;
    const int lane = tid & 31;
    const int warp = tid >> 5;
    const int wm = warp >> 2;
    const int wn = warp & 3;
    const int g  = lane >> 2;
    const int t4 = lane & 3;

    const float* gA[4]; uint32_t sAoff[4];
    const float* gB[4];
#pragma unroll
    for (int r = 0; r < 4; r++) {
        int id = tid + r * 256;
        int k = id >> 5, m4 = (id & 31) << 2;
        gA[r] = A + (long)(k0 + k) * CDIM + tm * 128 + m4;
        sAoff[r] = k * 136 + m4;
        gB[r] = A + (long)(k0 + k) * CDIM + tn * 128 + m4;
    }
    const long stepA = (long)32 * CDIM;

    const uint32_t sAb = (uint32_t)__cvta_generic_to_shared(As);
    const uint32_t sBb = (uint32_t)__cvta_generic_to_shared(Bs);

    auto issue = [&](int buf) {
#pragma unroll
        for (int r = 0; r < 4; r++) { cp16(sAb + (buf * AW + sAoff[r]) * 4, gA[r]); gA[r] += stepA; }
        if (!same) {
#pragma unroll
            for (int r = 0; r < 4; r++) { cp16(sBb + (buf * BW + sAoff[r]) * 4, gB[r]); gB[r] += stepA; }
        }
        asm volatile("cp.async.commit_group;");
    };

    float acc[4][4][4];
#pragma unroll
    for (int i = 0; i < 4; i++)
#pragma unroll
        for (int j = 0; j < 4; j++)
#pragma unroll
            for (int r = 0; r < 4; r++) acc[i][j][r] = 0.f;

    const int T = kChunk >> 5;
    issue(0);
    if (T > 1) issue(1);
    int buf = 0;
    for (int t = 0; t < T; t++) {
        if (t + 2 < T) {
            issue((buf + 2) % 3);
            asm volatile("cp.async.wait_group 2;");
        } else if (t + 1 < T) {
            asm volatile("cp.async.wait_group 1;");
        } else {
            asm volatile("cp.async.wait_group 0;");
        }
        __syncthreads();
        const float* Ab = As + buf * AW;
        const float* Bb = same ? Ab : (Bs + buf * BW);
#pragma unroll
        for (int ks = 0; ks < 32; ks += 8) {
            uint32_t af[4][4], bf[4][2];
#pragma unroll
            for (int mi = 0; mi < 4; mi++) {
                int m0 = wm * 64 + mi * 16;
                af[mi][0] = f2tf(Ab[(ks + t4) * 136 + m0 + g]);
                af[mi][1] = f2tf(Ab[(ks + t4) * 136 + m0 + g + 8]);
                af[mi][2] = f2tf(Ab[(ks + t4 + 4) * 136 + m0 + g]);
                af[mi][3] = f2tf(Ab[(ks + t4 + 4) * 136 + m0 + g + 8]);
            }
#pragma unroll
            for (int ni = 0; ni < 4; ni++) {
                int n0 = wn * 32 + ni * 8;
                bf[ni][0] = f2tf(Bb[(ks + t4) * 136 + n0 + g]);
                bf[ni][1] = f2tf(Bb[(ks + t4 + 4) * 136 + n0 + g]);
            }
#pragma unroll
            for (int mi = 0; mi < 4; mi++)
#pragma unroll
                for (int ni = 0; ni < 4; ni++)
                    mma8(acc[mi][ni], af[mi], bf[ni]);
        }
        __syncthreads();
        buf = (buf + 1) % 3;
    }

    const bool mirror = (tm != tn);
#pragma unroll
    for (int mi = 0; mi < 4; mi++) {
#pragma unroll
        for (int ni = 0; ni < 4; ni++) {
            int row = (tm << 7) + wm * 64 + mi * 16 + g;
            int col = (tn << 7) + wn * 32 + ni * 8 + t4 * 2;
            atomicAdd(&Cp[(long)row * CDIM + col],           acc[mi][ni][0]);
            atomicAdd(&Cp[(long)row * CDIM + col + 1],       acc[mi][ni][1]);
            atomicAdd(&Cp[(long)(row + 8) * CDIM + col],     acc[mi][ni][2]);
            atomicAdd(&Cp[(long)(row + 8) * CDIM + col + 1], acc[mi][ni][3]);
            if (mirror) {
                atomicAdd(&Cp[(long)col * CDIM + row],           acc[mi][ni][0]);
                atomicAdd(&Cp[(long)(col + 1) * CDIM + row],     acc[mi][ni][1]);
                atomicAdd(&Cp[(long)col * CDIM + row + 8],       acc[mi][ni][2]);
                atomicAdd(&Cp[(long)(col + 1) * CDIM + row + 8], acc[mi][ni][3]);
            }
        }
    }
}

// ---------------------------------------------------------------------------
// qk_kernel (R15): Yqk[bh][mb*64..+64][0..63] = G(mb rows) @ [Wq_h | Wk_h].
// ---------------------------------------------------------------------------
__global__ __launch_bounds__(256) void qk_kernel(
    const float* __restrict__ Gg, const float* __restrict__ Wq,
    const float* __restrict__ Wk, float* __restrict__ Yqk)
{
    extern __shared__ uint32_t smw[];
    uint32_t* SW = smw;           // 256 x 64, stride 72 (tf32)
    uint32_t* SG = smw + 18432;   // 64 x 256, stride 260 (tf32)

    const int h  = blockIdx.x;
    const int mb = blockIdx.y;
    const int b  = blockIdx.z;
    const int bh = b * HEADS + h;
    const float* G = Gg + (long)b * CDIM * CDIM;

    const int tid  = threadIdx.x;
    const int lane = tid & 31;
    const int warp = tid >> 5;
    const int g  = lane >> 2;
    const int t4 = lane & 3;

    for (int i = tid; i < 256 * 64; i += 256) {
        int k = i >> 6, n = i & 63;
        float v = (n < 32) ? Wq[k * CDIM + h * 32 + n]
                           : Wk[k * CDIM + h * 32 + (n - 32)];
        SW[k * 72 + n] = f2tf(v);
    }
    for (int i = tid; i < 4096; i += 256) {
        int row = i >> 6, c4 = (i & 63) << 2;
        float4 v = *(const float4*)(G + (long)(mb * 64 + row) * 256 + c4);
        uint32_t* d = SG + row * 260 + c4;
        d[0] = f2tf(v.x); d[1] = f2tf(v.y); d[2] = f2tf(v.z); d[3] = f2tf(v.w);
    }
    __syncthreads();

    const int m0 = (warp & 3) * 16;
    const int n0 = (warp >> 2) * 32;
    float acc[4][4];
#pragma unroll
    for (int i = 0; i < 4; i++)
#pragma unroll
        for (int r = 0; r < 4; r++) acc[i][r] = 0.f;
#pragma unroll 8
    for (int ks = 0; ks < 256; ks += 8) {
        uint32_t af[4], bf[4][2];
        af[0] = SG[(m0 + g) * 260 + ks + t4];
        af[1] = SG[(m0 + g + 8) * 260 + ks + t4];
        af[2] = SG[(m0 + g) * 260 + ks + t4 + 4];
        af[3] = SG[(m0 + g + 8) * 260 + ks + t4 + 4];
#pragma unroll
        for (int nf = 0; nf < 4; nf++) {
            int nn = n0 + nf * 8;
            bf[nf][0] = SW[(ks + t4) * 72 + nn + g];
            bf[nf][1] = SW[(ks + t4 + 4) * 72 + nn + g];
        }
#pragma unroll
        for (int nf = 0; nf < 4; nf++) mma8(acc[nf], af, bf[nf]);
    }

    float* Y = Yqk + (long)bh * 256 * 64;
#pragma unroll
    for (int nf = 0; nf < 4; nf++) {
        int nn = n0 + nf * 8 + t4 * 2;
        int rr = mb * 64 + m0 + g;
        *(float2*)&Y[rr * 64 + nn]       = make_float2(acc[nf][0], acc[nf][1]);
        *(float2*)&Y[(rr + 8) * 64 + nn] = make_float2(acc[nf][2], acc[nf][3]);
    }
}

// ---------------------------------------------------------------------------
// mid_kernel (R15): per (h,b): Mm via mma, diag reduce, softmax, Wmix,
// Weff += Wv@Wmix (atomics).
// ---------------------------------------------------------------------------
__global__ __launch_bounds__(256) void mid_kernel(
    const float* __restrict__ Yqk, const float* __restrict__ Wq,
    const float* __restrict__ Wk, const float* __restrict__ Wv,
    const float* __restrict__ Wout, float* __restrict__ Weff)
{
    extern __shared__ uint32_t smw[];
    uint32_t* SW = smw;
    uint32_t* SY = smw + 18432;
    float* SMM  = (float*)(smw + 36864);
    float* SATT = (float*)(smw + 37920);
    float* SDQ  = (float*)(smw + 38976);
    float* SDK  = (float*)(smw + 39008);
    float* DP   = (float*)(smw + 39040);

    const int h = blockIdx.x;
    const int b = blockIdx.z;
    const int bh = b * HEADS + h;
    float* Wf = Weff + (long)b * CDIM * CDIM;

    const int tid  = threadIdx.x;
    const int lane = tid & 31;
    const int warp = tid >> 5;
    const int g  = lane >> 2;
    const int t4 = lane & 3;

    for (int i = tid; i < 256 * 64; i += 256) {
        int k = i >> 6, n = i & 63;
        float v = (n < 32) ? Wq[k * CDIM + h * 32 + n]
                           : Wk[k * CDIM + h * 32 + (n - 32)];
        SW[k * 72 + n] = f2tf(v);
    }
    const float* Y = Yqk + (long)bh * 256 * 64;
    for (int i = tid; i < 256 * 64; i += 256) {
        int m = i >> 6, n = i & 63;
        SY[m * 72 + n] = __float_as_uint(Y[i]);
    }
    __syncthreads();

    {
        const int c0 = (warp & 1) * 16;
        const int e0 = (warp >> 1) * 8;
        float macc[4] = {0.f, 0.f, 0.f, 0.f};
#pragma unroll 8
        for (int ks = 0; ks < 256; ks += 8) {
            uint32_t af[4], bf[2];
            af[0] = SW[(ks + t4) * 72 + c0 + g];
            af[1] = SW[(ks + t4) * 72 + c0 + g + 8];
            af[2] = SW[(ks + t4 + 4) * 72 + c0 + g];
            af[3] = SW[(ks + t4 + 4) * 72 + c0 + g + 8];
            bf[0] = f2tf(__uint_as_float(SY[(ks + t4) * 72 + 32 + e0 + g]));
            bf[1] = f2tf(__uint_as_float(SY[(ks + t4 + 4) * 72 + 32 + e0 + g]));
            mma8(macc, af, bf);
        }
        int cc = c0 + g, ee = e0 + 2 * t4;
        SMM[cc * 33 + ee]           = macc[0];
        SMM[cc * 33 + ee + 1]       = macc[1];
        SMM[(cc + 8) * 33 + ee]     = macc[2];
        SMM[(cc + 8) * 33 + ee + 1] = macc[3];
    }

    {
        int c = tid & 63, seg = tid >> 6;
        float s = 0.f;
        int mbeg = seg * 64;
#pragma unroll 8
        for (int m = 0; m < 64; m++)
            s += __uint_as_float(SW[(mbeg + m) * 72 + c]) *
                 __uint_as_float(SY[(mbeg + m) * 72 + c]);
        DP[seg * 64 + c] = s;
    }
    __syncthreads();
    if (tid < 32) {
        SDQ[tid] = DP[tid] + DP[64 + tid] + DP[128 + tid] + DP[192 + tid];
    } else if (tid < 64) {
        int c = tid;
        SDK[c - 32] = DP[c] + DP[64 + c] + DP[128 + c] + DP[192 + c];
    }
    __syncthreads();

    {
        float nk = rsqrtf(SDK[lane]);
#pragma unroll
        for (int r = 0; r < 4; r++) {
            int c = warp * 4 + r;
            float nq = rsqrtf(SDQ[c]);
            float l = SMM[c * 33 + lane] * nq * nk * (1.0f / 128.0f);
            float mx = l;
            for (int o = 16; o; o >>= 1) mx = fmaxf(mx, __shfl_xor_sync(0xffffffffu, mx, o));
            float p = __expf(l - mx);
            float s = p;
            for (int o = 16; o; o >>= 1) s += __shfl_xor_sync(0xffffffffu, s, o);
            SATT[c * 33 + lane] = p / s;
        }
    }
    __syncthreads();

    uint32_t* SWv = smw;
    uint32_t* SWx = smw + 9216;
    {
        float wo[32];
#pragma unroll
        for (int c = 0; c < 32; c++) wo[c] = Wout[(h * 32 + c) * CDIM + tid];
        for (int e = 0; e < 32; e++) {
            float a = 0.f;
#pragma unroll
            for (int c = 0; c < 32; c++) a += SATT[c * 33 + e] * wo[c];
            SWx[e * 264 + tid] = f2tf(a);
        }
        for (int i = tid; i < 8192; i += 256) {
            int m = i >> 5, e = i & 31;
            SWv[m * 36 + e] = f2tf(Wv[m * CDIM + h * 32 + e]);
        }
    }
    __syncthreads();

    {
        const int m0w = warp * 32;
        for (int nc = 0; nc < 4; nc++) {
            float acc[2][8][4];
#pragma unroll
            for (int mi = 0; mi < 2; mi++)
#pragma unroll
                for (int nf = 0; nf < 8; nf++)
#pragma unroll
                    for (int r = 0; r < 4; r++) acc[mi][nf][r] = 0.f;
#pragma unroll
            for (int ks = 0; ks < 32; ks += 8) {
                uint32_t af[2][4];
#pragma unroll
                for (int mi = 0; mi < 2; mi++) {
                    int mm = m0w + mi * 16;
                    af[mi][0] = SWv[(mm + g) * 36 + ks + t4];
                    af[mi][1] = SWv[(mm + g + 8) * 36 + ks + t4];
                    af[mi][2] = SWv[(mm + g) * 36 + ks + t4 + 4];
                    af[mi][3] = SWv[(mm + g + 8) * 36 + ks + t4 + 4];
                }
#pragma unroll
                for (int nf = 0; nf < 8; nf++) {
                    int nn = nc * 64 + nf * 8 + g;
                    uint32_t bf[2];
                    bf[0] = SWx[(ks + t4) * 264 + nn];
                    bf[1] = SWx[(ks + t4 + 4) * 264 + nn];
                    mma8(acc[0][nf], af[0], bf);
                    mma8(acc[1][nf], af[1], bf);
                }
            }
#pragma unroll
            for (int mi = 0; mi < 2; mi++) {
#pragma unroll
                for (int nf = 0; nf < 8; nf++) {
                    int rr = m0w + mi * 16 + g;
                    int cc = nc * 64 + nf * 8 + t4 * 2;
                    atomicAdd(&Wf[rr * 256 + cc],           acc[mi][nf][0]);
                    atomicAdd(&Wf[rr * 256 + cc + 1],       acc[mi][nf][1]);
                    atomicAdd(&Wf[(rr + 8) * 256 + cc],     acc[mi][nf][2]);
                    atomicAdd(&Wf[(rr + 8) * 256 + cc + 1], acc[mi][nf][3]);
                }
            }
        }
    }
}

// ---------------------------------------------------------------------------
// WeffTh[b][n][k] = fp16(Weff[b][k][n])  (tiled transpose + RN convert)
// ---------------------------------------------------------------------------
__global__ void weffT_kernel(const float* __restrict__ Weff,
                             __half* __restrict__ WeffT)
{
    __shared__ float t[32][33];
    const int x0 = blockIdx.x * 32;     // n-tile
    const int y0 = blockIdx.y * 32;     // k-tile
    const int b  = blockIdx.z;
    const float* Wi = Weff + (long)b * CDIM * CDIM;
    __half* Wo = WeffT + (long)b * CDIM * CDIM;
    const int tx = threadIdx.x, ty = threadIdx.y;
    for (int j = ty; j < 32; j += 8)
        t[j][tx] = Wi[(y0 + j) * CDIM + x0 + tx];
    __syncthreads();
    for (int j = ty; j < 32; j += 8)
        Wo[(long)(x0 + j) * CDIM + y0 + tx] = __float2half_rn(t[tx][j]);
}

// ---------------------------------------------------------------------------
// out = X @ Weff (fp16 operands, fp32 accum).  128 threads, CTA 128x128,
// warp 64x64 (2x2), m16n8k16.
// B (WeffTh [n][k] fp16): loaded ONCE via cp.async, smem-resident,
//   stride 272 halves (544B) -> conflict-free LDS.64.
// A (x fp32): register-staged LDG.128 -> cvt fp16 -> STS.64, single smem
//   buffer, stride 48 halves (96B) -> conflict-free LDS.64.
// k-permutation: logical k16-pairs {t4, t4+4} <- physical pairs {2t4, 2t4+1}
//   (one LDS.64 per fragment pair; consistent across A and B).
// ---------------------------------------------------------------------------
__global__ __launch_bounds__(128, 2) void out_gemm(
    const float* __restrict__ xg, const __half* __restrict__ wT,
    float* __restrict__ outg)
{
    extern __shared__ char smemc[];
    char* Bh = smemc;                  // 128 x 544B = 69632
    char* Ah = smemc + 69632;          // 128 x 96B  = 12288

    const int tid  = threadIdx.x;
    const int lane = tid & 31;
    const int warp = tid >> 5;
    const int wm = warp >> 1, wn = warp & 1;
    const int g  = lane >> 2, t4 = lane & 3;
    const int b  = blockIdx.z;
    const int tm = blockIdx.x >> 1, tn = blockIdx.x & 1;

    const float*  xb = xg + ((long)b * HW + (long)tm * 128) * CDIM;
    const __half* wb = wT + (long)b * CDIM * CDIM + (long)tn * 128 * CDIM;

    const uint32_t sB = (uint32_t)__cvta_generic_to_shared(Bh);

    // one-time B load: 128 rows x 512B, stride 544B
    {
#pragma unroll
        for (int r = 0; r < 32; r++) {
            int id = tid + r * 128;
            int row = id >> 5, chunk = id & 31;
            cp16(sB + row * 544 + chunk * 16, wb + (long)row * CDIM + chunk * 8);
        }
        asm volatile("cp.async.commit_group;");
    }

    // register staging for A
    float4 vreg[8];
    auto loadA = [&](int kt) {
#pragma unroll
        for (int r = 0; r < 8; r++) {
            int id = tid + r * 128;
            int row = id >> 3, c4 = id & 7;
            vreg[r] = *(const float4*)(xb + (long)row * CDIM + kt * 32 + c4 * 4);
        }
    };
    auto stsA = [&]() {
#pragma unroll
        for (int r = 0; r < 8; r++) {
            int id = tid + r * 128;
            int row = id >> 3, c4 = id & 7;
            __half2 h0 = __floats2half2_rn(vreg[r].x, vreg[r].y);
            __half2 h1 = __floats2half2_rn(vreg[r].z, vreg[r].w);
            uint2 u;
            u.x = *(uint32_t*)&h0;
            u.y = *(uint32_t*)&h1;
            *(uint2*)(Ah + row * 96 + c4 * 8) = u;
        }
    };

    float acc[4][8][4];
#pragma unroll
    for (int i = 0; i < 4; i++)
#pragma unroll
        for (int j = 0; j < 8; j++)
#pragma unroll
            for (int r = 0; r < 4; r++) acc[i][j][r] = 0.f;

    loadA(0);
    asm volatile("cp.async.wait_group 0;");   // B resident

    for (int kt = 0; kt < 8; kt++) {
        stsA();
        __syncthreads();
        if (kt + 1 < 8) loadA(kt + 1);        // LDG in flight during consume
#pragma unroll
        for (int d = 0; d < 2; d++) {
            uint2 qa[4][2];
#pragma unroll
            for (int mi = 0; mi < 4; mi++) {
                int r1 = wm * 64 + mi * 16 + g;
                qa[mi][0] = *(const uint2*)(Ah + r1 * 96 + d * 32 + 8 * t4);
                qa[mi][1] = *(const uint2*)(Ah + (r1 + 8) * 96 + d * 32 + 8 * t4);
            }
#pragma unroll
            for (int ni = 0; ni < 8; ni++) {
                int nr = wn * 64 + ni * 8 + g;
                uint2 qb = *(const uint2*)(Bh + nr * 544 + kt * 64 + d * 32 + 8 * t4);
#pragma unroll
                for (int mi = 0; mi < 4; mi++)
                    mma16(acc[mi][ni],
                          qa[mi][0].x, qa[mi][1].x, qa[mi][0].y, qa[mi][1].y,
                          qb.x, qb.y);
            }
        }
        __syncthreads();
    }

    float* ob = outg + ((long)b * HW + (long)tm * 128) * CDIM + (long)tn * 128;
#pragma unroll
    for (int mi = 0; mi < 4; mi++) {
        int r1 = wm * 64 + mi * 16 + g;
#pragma unroll
        for (int ni = 0; ni < 8; ni++) {
            int cc = wn * 64 + ni * 8 + 2 * t4;
            *(float2*)&ob[(long)r1 * CDIM + cc]       = make_float2(acc[mi][ni][0], acc[mi][ni][1]);
            *(float2*)&ob[(long)(r1 + 8) * CDIM + cc] = make_float2(acc[mi][ni][2], acc[mi][ni][3]);
        }
    }
}

// ---------------------------------------------------------------------------
extern "C" void kernel_launch(void* const* d_in, const int* in_sizes, int n_in,
                              void* d_out, int out_size) {
    (void)in_sizes; (void)n_in; (void)out_size;
    const float* x    = (const float*)d_in[0];
    const float* Wq   = (const float*)d_in[1];
    const float* Wk   = (const float*)d_in[2];
    const float* Wv   = (const float*)d_in[3];
    const float* Wout = (const float*)d_in[4];
    float* out = (float*)d_out;

    float *G, *Weff, *Yqk;
    __half* WeffTh;
    cudaGetSymbolAddress((void**)&G,      g_G);
    cudaGetSymbolAddress((void**)&Weff,   g_Weff);
    cudaGetSymbolAddress((void**)&WeffTh, g_WeffTh);
    cudaGetSymbolAddress((void**)&Yqk,    g_Yqk);

    const int smemGram = 6 * 4352 * 4;    // 104448
    const int smemQK   = 35072 * 4;       // 140288
    const int smemMid  = 39296 * 4;       // 157184
    const int smemOut  = 69632 + 12288;   // 81920

    cudaFuncSetAttribute(gram_gemm,
                         cudaFuncAttributeMaxDynamicSharedMemorySize, smemGram);
    cudaFuncSetAttribute(qk_kernel,
                         cudaFuncAttributeMaxDynamicSharedMemorySize, smemQK);
    cudaFuncSetAttribute(mid_kernel,
                         cudaFuncAttributeMaxDynamicSharedMemorySize, smemMid);
    cudaFuncSetAttribute(out_gemm,
                         cudaFuncAttributeMaxDynamicSharedMemorySize, smemOut);

    cudaMemsetAsync(G,    0, BATCH * CDIM * CDIM * sizeof(float));
    cudaMemsetAsync(Weff, 0, BATCH * CDIM * CDIM * sizeof(float));

    // G[b] = X_b^T X_b
    {
        dim3 gr(3 * 32, 1, BATCH);
        gram_gemm<<<gr, 256, smemGram>>>(x, G, 512);
    }
    // Yqk = G @ [Wq_h|Wk_h]
    {
        dim3 gr(HEADS, 4, BATCH);
        qk_kernel<<<gr, 256, smemQK>>>(G, Wq, Wk, Yqk);
    }
    // Mm/softmax/Wmix/Weff
    {
        dim3 gr(HEADS, 1, BATCH);
        mid_kernel<<<gr, 256, smemMid>>>(Yqk, Wq, Wk, Wv, Wout, Weff);
    }
    // WeffTh = fp16(Weff^T)
    {
        dim3 gr(8, 8, BATCH), bl(32, 8);
        weffT_kernel<<<gr, bl>>>(Weff, WeffTh);
    }
    // out = X @ Weff (fp16 mma)
    {
        dim3 gr(128 * 2, 1, BATCH);
        out_gemm<<<gr, 128, smemOut>>>(x, WeffTh, out);
    }
}

// round 17
// speedup vs baseline: 1.3673x; 1.1172x over previous
#include <cuda_runtime.h>
#include <cuda_fp16.h>
#include <cstdint>

#define BATCH 4
#define HW    16384
#define CDIM  256
#define HEADS 8

__device__ float  g_G[BATCH * CDIM * CDIM];
__device__ float  g_Weff[BATCH * CDIM * CDIM];
__device__ __half g_WeffTh[BATCH * CDIM * CDIM];         // [n][k] fp16
__device__ float  g_Yqk[BATCH * HEADS * CDIM * 64];      // [bh][m][64] raw fp32

__device__ __forceinline__ uint32_t f2tf(float x) {
    uint32_t r;
    asm("cvt.rna.tf32.f32 %0, %1;" : "=r"(r) : "f"(x));
    return r;
}

__device__ __forceinline__ uint32_t packh2(float a, float b) {
    __half2 h = __floats2half2_rn(a, b);
    return *(uint32_t*)&h;
}

__device__ __forceinline__ void mma8(float* c, const uint32_t* a, const uint32_t* b) {
    asm volatile(
        "mma.sync.aligned.m16n8k8.row.col.f32.tf32.tf32.f32 "
        "{%0,%1,%2,%3}, {%4,%5,%6,%7}, {%8,%9}, {%0,%1,%2,%3};"
        : "+f"(c[0]), "+f"(c[1]), "+f"(c[2]), "+f"(c[3])
        : "r"(a[0]), "r"(a[1]), "r"(a[2]), "r"(a[3]), "r"(b[0]), "r"(b[1]));
}

// fp16 mma, fp32 accumulate
__device__ __forceinline__ void mma16(float* c, uint32_t a0, uint32_t a1,
                                      uint32_t a2, uint32_t a3,
                                      uint32_t b0, uint32_t b1) {
    asm volatile(
        "mma.sync.aligned.m16n8k16.row.col.f32.f16.f16.f32 "
        "{%0,%1,%2,%3}, {%4,%5,%6,%7}, {%8,%9}, {%0,%1,%2,%3};"
        : "+f"(c[0]), "+f"(c[1]), "+f"(c[2]), "+f"(c[3])
        : "r"(a0), "r"(a1), "r"(a2), "r"(a3), "r"(b0), "r"(b1));
}

__device__ __forceinline__ void cp16(uint32_t s, const void* g) {
    asm volatile("cp.async.cg.shared.global [%0], [%1], 16;" :: "r"(s), "l"(g));
}

// ---------------------------------------------------------------------------
// Gram fp16: G[b] = X_b^T X_b.  256 threads, CTA 128x128, warp 64x32 (2x4),
// m16n8k16. SYM 3-tile + mirror + diag B-alias, split-K 32 (kChunk 512).
// Pair-interleaved smem: word(kp, m) = half2{ x[2kp][m], x[2kp+1][m] },
// row stride 136 words -> every fragment is one conflict-free LDS.32.
// Staging: register-prefetched LDG.128, double-buffered smem (1 bar/tile).
// k-permutation (slot0 <- pair t4, slot1 <- pair t4+4) consistent A<->B.
// ---------------------------------------------------------------------------
__global__ __launch_bounds__(256, 2) void gram_gemm(
    const float* __restrict__ xg, float* __restrict__ Gg, int kChunk)
{
    extern __shared__ uint32_t smw[];   // 2 stages x (A 2176 + B 2176) words

    const int tileId = blockIdx.x % 3;
    const int split  = blockIdx.x / 3;
    const int tm = (tileId == 2) ? 1 : 0;
    const int tn = (tileId == 0) ? 0 : 1;
    const bool same = (tm == tn);

    const float* Ax = xg + (long)blockIdx.z * HW * CDIM;
    float* Cp = Gg + (long)blockIdx.z * CDIM * CDIM;

    const int k0 = split * kChunk;

    const int tid  = threadIdx.x;
    const int lane = tid & 31;
    const int warp = tid >> 5;
    const int wm = warp >> 2;        // 0..1
    const int wn = warp & 3;         // 0..3
    const int g  = lane >> 2;
    const int t4 = lane & 3;

    // staging index map: idx r*256+tid -> (kp, m4)
    const int kpA[2] = { tid >> 5, (tid + 256) >> 5 };
    const int m4A[2] = { (tid & 31) << 2, ((tid + 256) & 31) << 2 };

    float4 va[2][2], vb[2][2];
    auto loadT = [&](int t) {
        long kk = k0 + t * 32;
#pragma unroll
        for (int r = 0; r < 2; r++) {
            const float* p = Ax + (kk + 2 * kpA[r]) * CDIM + tm * 128 + m4A[r];
            va[r][0] = *(const float4*)p;
            va[r][1] = *(const float4*)(p + CDIM);
            if (!same) {
                const float* q = Ax + (kk + 2 * kpA[r]) * CDIM + tn * 128 + m4A[r];
                vb[r][0] = *(const float4*)q;
                vb[r][1] = *(const float4*)(q + CDIM);
            }
        }
    };
    auto stsT = [&](int st) {
        uint32_t* PA = smw + st * 4352;
        uint32_t* PB = same ? PA : (PA + 2176);
#pragma unroll
        for (int r = 0; r < 2; r++) {
            uint4 w;
            w.x = packh2(va[r][0].x, va[r][1].x);
            w.y = packh2(va[r][0].y, va[r][1].y);
            w.z = packh2(va[r][0].z, va[r][1].z);
            w.w = packh2(va[r][0].w, va[r][1].w);
            *(uint4*)&PA[kpA[r] * 136 + m4A[r]] = w;
            if (!same) {
                uint4 u;
                u.x = packh2(vb[r][0].x, vb[r][1].x);
                u.y = packh2(vb[r][0].y, vb[r][1].y);
                u.z = packh2(vb[r][0].z, vb[r][1].z);
                u.w = packh2(vb[r][0].w, vb[r][1].w);
                *(uint4*)&PB[kpA[r] * 136 + m4A[r]] = u;
            }
        }
    };

    float acc[4][4][4];
#pragma unroll
    for (int i = 0; i < 4; i++)
#pragma unroll
        for (int j = 0; j < 4; j++)
#pragma unroll
            for (int r = 0; r < 4; r++) acc[i][j][r] = 0.f;

    const int T = kChunk >> 5;
    loadT(0);
    stsT(0);
    for (int t = 0; t < T; t++) {
        if (t + 1 < T) loadT(t + 1);
        __syncthreads();
        const uint32_t* PA = smw + (t & 1) * 4352;
        const uint32_t* PB = same ? PA : (PA + 2176);
#pragma unroll
        for (int d = 0; d < 2; d++) {
            const int r0 = (d * 8 + t4) * 136;
            const int r1 = (d * 8 + 4 + t4) * 136;
            uint32_t af[4][4];
#pragma unroll
            for (int mi = 0; mi < 4; mi++) {
                int m0 = wm * 64 + mi * 16 + g;
                af[mi][0] = PA[r0 + m0];
                af[mi][1] = PA[r0 + m0 + 8];
                af[mi][2] = PA[r1 + m0];
                af[mi][3] = PA[r1 + m0 + 8];
            }
#pragma unroll
            for (int ni = 0; ni < 4; ni++) {
                int n0 = wn * 32 + ni * 8 + g;
                uint32_t b0 = PB[r0 + n0];
                uint32_t b1 = PB[r1 + n0];
#pragma unroll
                for (int mi = 0; mi < 4; mi++)
                    mma16(acc[mi][ni], af[mi][0], af[mi][1], af[mi][2], af[mi][3], b0, b1);
            }
        }
        if (t + 1 < T) stsT((t + 1) & 1);
    }

    const bool mirror = (tm != tn);
#pragma unroll
    for (int mi = 0; mi < 4; mi++) {
#pragma unroll
        for (int ni = 0; ni < 4; ni++) {
            int row = (tm << 7) + wm * 64 + mi * 16 + g;
            int col = (tn << 7) + wn * 32 + ni * 8 + t4 * 2;
            atomicAdd(&Cp[(long)row * CDIM + col],           acc[mi][ni][0]);
            atomicAdd(&Cp[(long)row * CDIM + col + 1],       acc[mi][ni][1]);
            atomicAdd(&Cp[(long)(row + 8) * CDIM + col],     acc[mi][ni][2]);
            atomicAdd(&Cp[(long)(row + 8) * CDIM + col + 1], acc[mi][ni][3]);
            if (mirror) {
                atomicAdd(&Cp[(long)col * CDIM + row],           acc[mi][ni][0]);
                atomicAdd(&Cp[(long)(col + 1) * CDIM + row],     acc[mi][ni][1]);
                atomicAdd(&Cp[(long)col * CDIM + row + 8],       acc[mi][ni][2]);
                atomicAdd(&Cp[(long)(col + 1) * CDIM + row + 8], acc[mi][ni][3]);
            }
        }
    }
}

// ---------------------------------------------------------------------------
// qk_kernel (R15): Yqk[bh][mb*64..+64][0..63] = G(mb rows) @ [Wq_h | Wk_h].
// ---------------------------------------------------------------------------
__global__ __launch_bounds__(256) void qk_kernel(
    const float* __restrict__ Gg, const float* __restrict__ Wq,
    const float* __restrict__ Wk, float* __restrict__ Yqk)
{
    extern __shared__ uint32_t smw[];
    uint32_t* SW = smw;           // 256 x 64, stride 72 (tf32)
    uint32_t* SG = smw + 18432;   // 64 x 256, stride 260 (tf32)

    const int h  = blockIdx.x;
    const int mb = blockIdx.y;
    const int b  = blockIdx.z;
    const int bh = b * HEADS + h;
    const float* G = Gg + (long)b * CDIM * CDIM;

    const int tid  = threadIdx.x;
    const int lane = tid & 31;
    const int warp = tid >> 5;
    const int g  = lane >> 2;
    const int t4 = lane & 3;

    for (int i = tid; i < 256 * 64; i += 256) {
        int k = i >> 6, n = i & 63;
        float v = (n < 32) ? Wq[k * CDIM + h * 32 + n]
                           : Wk[k * CDIM + h * 32 + (n - 32)];
        SW[k * 72 + n] = f2tf(v);
    }
    for (int i = tid; i < 4096; i += 256) {
        int row = i >> 6, c4 = (i & 63) << 2;
        float4 v = *(const float4*)(G + (long)(mb * 64 + row) * 256 + c4);
        uint32_t* d = SG + row * 260 + c4;
        d[0] = f2tf(v.x); d[1] = f2tf(v.y); d[2] = f2tf(v.z); d[3] = f2tf(v.w);
    }
    __syncthreads();

    const int m0 = (warp & 3) * 16;
    const int n0 = (warp >> 2) * 32;
    float acc[4][4];
#pragma unroll
    for (int i = 0; i < 4; i++)
#pragma unroll
        for (int r = 0; r < 4; r++) acc[i][r] = 0.f;
#pragma unroll 8
    for (int ks = 0; ks < 256; ks += 8) {
        uint32_t af[4], bf[4][2];
        af[0] = SG[(m0 + g) * 260 + ks + t4];
        af[1] = SG[(m0 + g + 8) * 260 + ks + t4];
        af[2] = SG[(m0 + g) * 260 + ks + t4 + 4];
        af[3] = SG[(m0 + g + 8) * 260 + ks + t4 + 4];
#pragma unroll
        for (int nf = 0; nf < 4; nf++) {
            int nn = n0 + nf * 8;
            bf[nf][0] = SW[(ks + t4) * 72 + nn + g];
            bf[nf][1] = SW[(ks + t4 + 4) * 72 + nn + g];
        }
#pragma unroll
        for (int nf = 0; nf < 4; nf++) mma8(acc[nf], af, bf[nf]);
    }

    float* Y = Yqk + (long)bh * 256 * 64;
#pragma unroll
    for (int nf = 0; nf < 4; nf++) {
        int nn = n0 + nf * 8 + t4 * 2;
        int rr = mb * 64 + m0 + g;
        *(float2*)&Y[rr * 64 + nn]       = make_float2(acc[nf][0], acc[nf][1]);
        *(float2*)&Y[(rr + 8) * 64 + nn] = make_float2(acc[nf][2], acc[nf][3]);
    }
}

// ---------------------------------------------------------------------------
// mid_kernel (R15): per (h,b): Mm via mma, diag reduce, softmax, Wmix,
// Weff += Wv@Wmix (atomics).
// ---------------------------------------------------------------------------
__global__ __launch_bounds__(256) void mid_kernel(
    const float* __restrict__ Yqk, const float* __restrict__ Wq,
    const float* __restrict__ Wk, const float* __restrict__ Wv,
    const float* __restrict__ Wout, float* __restrict__ Weff)
{
    extern __shared__ uint32_t smw[];
    uint32_t* SW = smw;
    uint32_t* SY = smw + 18432;
    float* SMM  = (float*)(smw + 36864);
    float* SATT = (float*)(smw + 37920);
    float* SDQ  = (float*)(smw + 38976);
    float* SDK  = (float*)(smw + 39008);
    float* DP   = (float*)(smw + 39040);

    const int h = blockIdx.x;
    const int b = blockIdx.z;
    const int bh = b * HEADS + h;
    float* Wf = Weff + (long)b * CDIM * CDIM;

    const int tid  = threadIdx.x;
    const int lane = tid & 31;
    const int warp = tid >> 5;
    const int g  = lane >> 2;
    const int t4 = lane & 3;

    for (int i = tid; i < 256 * 64; i += 256) {
        int k = i >> 6, n = i & 63;
        float v = (n < 32) ? Wq[k * CDIM + h * 32 + n]
                           : Wk[k * CDIM + h * 32 + (n - 32)];
        SW[k * 72 + n] = f2tf(v);
    }
    const float* Y = Yqk + (long)bh * 256 * 64;
    for (int i = tid; i < 256 * 64; i += 256) {
        int m = i >> 6, n = i & 63;
        SY[m * 72 + n] = __float_as_uint(Y[i]);
    }
    __syncthreads();

    {
        const int c0 = (warp & 1) * 16;
        const int e0 = (warp >> 1) * 8;
        float macc[4] = {0.f, 0.f, 0.f, 0.f};
#pragma unroll 8
        for (int ks = 0; ks < 256; ks += 8) {
            uint32_t af[4], bf[2];
            af[0] = SW[(ks + t4) * 72 + c0 + g];
            af[1] = SW[(ks + t4) * 72 + c0 + g + 8];
            af[2] = SW[(ks + t4 + 4) * 72 + c0 + g];
            af[3] = SW[(ks + t4 + 4) * 72 + c0 + g + 8];
            bf[0] = f2tf(__uint_as_float(SY[(ks + t4) * 72 + 32 + e0 + g]));
            bf[1] = f2tf(__uint_as_float(SY[(ks + t4 + 4) * 72 + 32 + e0 + g]));
            mma8(macc, af, bf);
        }
        int cc = c0 + g, ee = e0 + 2 * t4;
        SMM[cc * 33 + ee]           = macc[0];
        SMM[cc * 33 + ee + 1]       = macc[1];
        SMM[(cc + 8) * 33 + ee]     = macc[2];
        SMM[(cc + 8) * 33 + ee + 1] = macc[3];
    }

    {
        int c = tid & 63, seg = tid >> 6;
        float s = 0.f;
        int mbeg = seg * 64;
#pragma unroll 8
        for (int m = 0; m < 64; m++)
            s += __uint_as_float(SW[(mbeg + m) * 72 + c]) *
                 __uint_as_float(SY[(mbeg + m) * 72 + c]);
        DP[seg * 64 + c] = s;
    }
    __syncthreads();
    if (tid < 32) {
        SDQ[tid] = DP[tid] + DP[64 + tid] + DP[128 + tid] + DP[192 + tid];
    } else if (tid < 64) {
        int c = tid;
        SDK[c - 32] = DP[c] + DP[64 + c] + DP[128 + c] + DP[192 + c];
    }
    __syncthreads();

    {
        float nk = rsqrtf(SDK[lane]);
#pragma unroll
        for (int r = 0; r < 4; r++) {
            int c = warp * 4 + r;
            float nq = rsqrtf(SDQ[c]);
            float l = SMM[c * 33 + lane] * nq * nk * (1.0f / 128.0f);
            float mx = l;
            for (int o = 16; o; o >>= 1) mx = fmaxf(mx, __shfl_xor_sync(0xffffffffu, mx, o));
            float p = __expf(l - mx);
            float s = p;
            for (int o = 16; o; o >>= 1) s += __shfl_xor_sync(0xffffffffu, s, o);
            SATT[c * 33 + lane] = p / s;
        }
    }
    __syncthreads();

    uint32_t* SWv = smw;
    uint32_t* SWx = smw + 9216;
    {
        float wo[32];
#pragma unroll
        for (int c = 0; c < 32; c++) wo[c] = Wout[(h * 32 + c) * CDIM + tid];
        for (int e = 0; e < 32; e++) {
            float a = 0.f;
#pragma unroll
            for (int c = 0; c < 32; c++) a += SATT[c * 33 + e] * wo[c];
            SWx[e * 264 + tid] = f2tf(a);
        }
        for (int i = tid; i < 8192; i += 256) {
            int m = i >> 5, e = i & 31;
            SWv[m * 36 + e] = f2tf(Wv[m * CDIM + h * 32 + e]);
        }
    }
    __syncthreads();

    {
        const int m0w = warp * 32;
        for (int nc = 0; nc < 4; nc++) {
            float acc[2][8][4];
#pragma unroll
            for (int mi = 0; mi < 2; mi++)
#pragma unroll
                for (int nf = 0; nf < 8; nf++)
#pragma unroll
                    for (int r = 0; r < 4; r++) acc[mi][nf][r] = 0.f;
#pragma unroll
            for (int ks = 0; ks < 32; ks += 8) {
                uint32_t af[2][4];
#pragma unroll
                for (int mi = 0; mi < 2; mi++) {
                    int mm = m0w + mi * 16;
                    af[mi][0] = SWv[(mm + g) * 36 + ks + t4];
                    af[mi][1] = SWv[(mm + g + 8) * 36 + ks + t4];
                    af[mi][2] = SWv[(mm + g) * 36 + ks + t4 + 4];
                    af[mi][3] = SWv[(mm + g + 8) * 36 + ks + t4 + 4];
                }
#pragma unroll
                for (int nf = 0; nf < 8; nf++) {
                    int nn = nc * 64 + nf * 8 + g;
                    uint32_t bf[2];
                    bf[0] = SWx[(ks + t4) * 264 + nn];
                    bf[1] = SWx[(ks + t4 + 4) * 264 + nn];
                    mma8(acc[0][nf], af[0], bf);
                    mma8(acc[1][nf], af[1], bf);
                }
            }
#pragma unroll
            for (int mi = 0; mi < 2; mi++) {
#pragma unroll
                for (int nf = 0; nf < 8; nf++) {
                    int rr = m0w + mi * 16 + g;
                    int cc = nc * 64 + nf * 8 + t4 * 2;
                    atomicAdd(&Wf[rr * 256 + cc],           acc[mi][nf][0]);
                    atomicAdd(&Wf[rr * 256 + cc + 1],       acc[mi][nf][1]);
                    atomicAdd(&Wf[(rr + 8) * 256 + cc],     acc[mi][nf][2]);
                    atomicAdd(&Wf[(rr + 8) * 256 + cc + 1], acc[mi][nf][3]);
                }
            }
        }
    }
}

// ---------------------------------------------------------------------------
// WeffTh[b][n][k] = fp16(Weff[b][k][n])  (tiled transpose + RN convert)
// ---------------------------------------------------------------------------
__global__ void weffT_kernel(const float* __restrict__ Weff,
                             __half* __restrict__ WeffT)
{
    __shared__ float t[32][33];
    const int x0 = blockIdx.x * 32;     // n-tile
    const int y0 = blockIdx.y * 32;     // k-tile
    const int b  = blockIdx.z;
    const float* Wi = Weff + (long)b * CDIM * CDIM;
    __half* Wo = WeffT + (long)b * CDIM * CDIM;
    const int tx = threadIdx.x, ty = threadIdx.y;
    for (int j = ty; j < 32; j += 8)
        t[j][tx] = Wi[(y0 + j) * CDIM + x0 + tx];
    __syncthreads();
    for (int j = ty; j < 32; j += 8)
        Wo[(long)(x0 + j) * CDIM + y0 + tx] = __float2half_rn(t[tx][j]);
}

// ---------------------------------------------------------------------------
// out = X @ Weff (fp16 operands, fp32 accum) — R16-proven (~48us).
// ---------------------------------------------------------------------------
__global__ __launch_bounds__(128, 2) void out_gemm(
    const float* __restrict__ xg, const __half* __restrict__ wT,
    float* __restrict__ outg)
{
    extern __shared__ char smemc[];
    char* Bh = smemc;                  // 128 x 544B = 69632
    char* Ah = smemc + 69632;          // 128 x 96B  = 12288

    const int tid  = threadIdx.x;
    const int lane = tid & 31;
    const int warp = tid >> 5;
    const int wm = warp >> 1, wn = warp & 1;
    const int g  = lane >> 2, t4 = lane & 3;
    const int b  = blockIdx.z;
    const int tm = blockIdx.x >> 1, tn = blockIdx.x & 1;

    const float*  xb = xg + ((long)b * HW + (long)tm * 128) * CDIM;
    const __half* wb = wT + (long)b * CDIM * CDIM + (long)tn * 128 * CDIM;

    const uint32_t sB = (uint32_t)__cvta_generic_to_shared(Bh);

    {
#pragma unroll
        for (int r = 0; r < 32; r++) {
            int id = tid + r * 128;
            int row = id >> 5, chunk = id & 31;
            cp16(sB + row * 544 + chunk * 16, wb + (long)row * CDIM + chunk * 8);
        }
        asm volatile("cp.async.commit_group;");
    }

    float4 vreg[8];
    auto loadA = [&](int kt) {
#pragma unroll
        for (int r = 0; r < 8; r++) {
            int id = tid + r * 128;
            int row = id >> 3, c4 = id & 7;
            vreg[r] = *(const float4*)(xb + (long)row * CDIM + kt * 32 + c4 * 4);
        }
    };
    auto stsA = [&]() {
#pragma unroll
        for (int r = 0; r < 8; r++) {
            int id = tid + r * 128;
            int row = id >> 3, c4 = id & 7;
            __half2 h0 = __floats2half2_rn(vreg[r].x, vreg[r].y);
            __half2 h1 = __floats2half2_rn(vreg[r].z, vreg[r].w);
            uint2 u;
            u.x = *(uint32_t*)&h0;
            u.y = *(uint32_t*)&h1;
            *(uint2*)(Ah + row * 96 + c4 * 8) = u;
        }
    };

    float acc[4][8][4];
#pragma unroll
    for (int i = 0; i < 4; i++)
#pragma unroll
        for (int j = 0; j < 8; j++)
#pragma unroll
            for (int r = 0; r < 4; r++) acc[i][j][r] = 0.f;

    loadA(0);
    asm volatile("cp.async.wait_group 0;");

    for (int kt = 0; kt < 8; kt++) {
        stsA();
        __syncthreads();
        if (kt + 1 < 8) loadA(kt + 1);
#pragma unroll
        for (int d = 0; d < 2; d++) {
            uint2 qa[4][2];
#pragma unroll
            for (int mi = 0; mi < 4; mi++) {
                int r1 = wm * 64 + mi * 16 + g;
                qa[mi][0] = *(const uint2*)(Ah + r1 * 96 + d * 32 + 8 * t4);
                qa[mi][1] = *(const uint2*)(Ah + (r1 + 8) * 96 + d * 32 + 8 * t4);
            }
#pragma unroll
            for (int ni = 0; ni < 8; ni++) {
                int nr = wn * 64 + ni * 8 + g;
                uint2 qb = *(const uint2*)(Bh + nr * 544 + kt * 64 + d * 32 + 8 * t4);
#pragma unroll
                for (int mi = 0; mi < 4; mi++)
                    mma16(acc[mi][ni],
                          qa[mi][0].x, qa[mi][1].x, qa[mi][0].y, qa[mi][1].y,
                          qb.x, qb.y);
            }
        }
        __syncthreads();
    }

    float* ob = outg + ((long)b * HW + (long)tm * 128) * CDIM + (long)tn * 128;
#pragma unroll
    for (int mi = 0; mi < 4; mi++) {
        int r1 = wm * 64 + mi * 16 + g;
#pragma unroll
        for (int ni = 0; ni < 8; ni++) {
            int cc = wn * 64 + ni * 8 + 2 * t4;
            *(float2*)&ob[(long)r1 * CDIM + cc]       = make_float2(acc[mi][ni][0], acc[mi][ni][1]);
            *(float2*)&ob[(long)(r1 + 8) * CDIM + cc] = make_float2(acc[mi][ni][2], acc[mi][ni][3]);
        }
    }
}

// ---------------------------------------------------------------------------
extern "C" void kernel_launch(void* const* d_in, const int* in_sizes, int n_in,
                              void* d_out, int out_size) {
    (void)in_sizes; (void)n_in; (void)out_size;
    const float* x    = (const float*)d_in[0];
    const float* Wq   = (const float*)d_in[1];
    const float* Wk   = (const float*)d_in[2];
    const float* Wv   = (const float*)d_in[3];
    const float* Wout = (const float*)d_in[4];
    float* out = (float*)d_out;

    float *G, *Weff, *Yqk;
    __half* WeffTh;
    cudaGetSymbolAddress((void**)&G,      g_G);
    cudaGetSymbolAddress((void**)&Weff,   g_Weff);
    cudaGetSymbolAddress((void**)&WeffTh, g_WeffTh);
    cudaGetSymbolAddress((void**)&Yqk,    g_Yqk);

    const int smemGram = 2 * 4352 * 4;    // 34816 (2 stages x (A+B) pair words)
    const int smemQK   = 35072 * 4;       // 140288
    const int smemMid  = 39296 * 4;       // 157184
    const int smemOut  = 69632 + 12288;   // 81920

    cudaFuncSetAttribute(gram_gemm,
                         cudaFuncAttributeMaxDynamicSharedMemorySize, smemGram);
    cudaFuncSetAttribute(qk_kernel,
                         cudaFuncAttributeMaxDynamicSharedMemorySize, smemQK);
    cudaFuncSetAttribute(mid_kernel,
                         cudaFuncAttributeMaxDynamicSharedMemorySize, smemMid);
    cudaFuncSetAttribute(out_gemm,
                         cudaFuncAttributeMaxDynamicSharedMemorySize, smemOut);

    cudaMemsetAsync(G,    0, BATCH * CDIM * CDIM * sizeof(float));
    cudaMemsetAsync(Weff, 0, BATCH * CDIM * CDIM * sizeof(float));

    // G[b] = X_b^T X_b  (fp16 mma, pair-interleaved smem)
    {
        dim3 gr(3 * 32, 1, BATCH);
        gram_gemm<<<gr, 256, smemGram>>>(x, G, 512);
    }
    // Yqk = G @ [Wq_h|Wk_h]
    {
        dim3 gr(HEADS, 4, BATCH);
        qk_kernel<<<gr, 256, smemQK>>>(G, Wq, Wk, Yqk);
    }
    // Mm/softmax/Wmix/Weff
    {
        dim3 gr(HEADS, 1, BATCH);
        mid_kernel<<<gr, 256, smemMid>>>(Yqk, Wq, Wk, Wv, Wout, Weff);
    }
    // WeffTh = fp16(Weff^T)
    {
        dim3 gr(8, 8, BATCH), bl(32, 8);
        weffT_kernel<<<gr, bl>>>(Weff, WeffTh);
    }
    // out = X @ Weff (fp16 mma)
    {
        dim3 gr(128 * 2, 1, BATCH);
        out_gemm<<<gr, 128, smemOut>>>(x, WeffTh, out);
    }
}